// round 2
// baseline (speedup 1.0000x reference)
#include <cuda_runtime.h>
#include <cuda_bf16.h>

#define EMB 64
#define MAXN 100000
#define MAXE 1000000
#define NLAYER 4

// ---------------- scratch (__device__ globals: allocation-free) ----------------
__device__ float g_h[(size_t)MAXN * 64];          // current node features (raw, pre-affine)
__device__ float g_agg[(size_t)MAXN * 64];        // scatter-add target
__device__ float g_y[(size_t)MAXN * 128];         // GEMM1 output
__device__ float g_stats[384];                    // [sum128, sq128, sum64, sq64]
__device__ float g_aff1[256];                     // BN1 affine: a[128], c[128]
__device__ float g_aff2[128];                     // outer BN affine: a[64], c[64]

// ---------------- init affine to identity (for layer 0 consumers) --------------
__global__ void init_aff_kernel() {
    int t = threadIdx.x;
    if (t < 64) g_aff2[t] = 1.0f;
    else        g_aff2[t] = 0.0f;   // t in [64,128)
}

// ---------------- atom encoder: h[n] = sum_c atom_emb[c][x[n,c]] ----------------
__global__ void atom_kernel(const int* __restrict__ x, const float* __restrict__ aemb, int N) {
    int t = blockIdx.x * blockDim.x + threadIdx.x;
    int node = t >> 4, lane = t & 15;
    if (node >= N) return;
    float4 s = make_float4(0.f, 0.f, 0.f, 0.f);
#pragma unroll
    for (int c = 0; c < 9; c++) {
        int v = __ldg(&x[node * 9 + c]);
        float4 e = *(const float4*)&aemb[((size_t)(c * 64 + v)) * 64 + lane * 4];
        s.x += e.x; s.y += e.y; s.z += e.z; s.w += e.w;
    }
    *(float4*)&g_h[(size_t)node * 64 + lane * 4] = s;
}

// ---------------- edge kernel: agg[dst] += relu(heff[src] + ee) -----------------
#define EPB 128   // edges per block (16 groups x 8 iters)
__global__ __launch_bounds__(256) void edge_kernel(const int* __restrict__ ei, const int* __restrict__ ea,
                            const float* __restrict__ bt /* 3*8*64 for this layer */,
                            int doRelu, int E, int N) {
    __shared__ float sbt[3 * 8 * 64];
    __shared__ float sa[64], sc[64];
    int tid = threadIdx.x;
    for (int t = tid; t < 1536; t += 256) sbt[t] = bt[t];
    if (tid < 64) { sa[tid] = g_aff2[tid]; sc[tid] = g_aff2[64 + tid]; }
    __syncthreads();

    int lane = tid & 15, grp = tid >> 4;
    int base = blockIdx.x * EPB;
    float4 a4 = *(float4*)&sa[lane * 4];
    float4 c4 = *(float4*)&sc[lane * 4];

#pragma unroll 1
    for (int i = 0; i < EPB / 16; i++) {
        int e = base + i * 16 + grp;
        if (e >= E) break;
        int src = __ldg(&ei[e]);
        int dst = __ldg(&ei[E + e]);
        int b0 = __ldg(&ea[e * 3 + 0]);
        int b1 = __ldg(&ea[e * 3 + 1]);
        int b2 = __ldg(&ea[e * 3 + 2]);
        float4 e0 = *(float4*)&sbt[(0 * 8 + b0) * 64 + lane * 4];
        float4 e1 = *(float4*)&sbt[(1 * 8 + b1) * 64 + lane * 4];
        float4 e2 = *(float4*)&sbt[(2 * 8 + b2) * 64 + lane * 4];
        float4 hv = __ldg((const float4*)&g_h[(size_t)src * 64 + lane * 4]);
        // affine + optional relu (previous layer's BN folded)
        float h0 = fmaf(a4.x, hv.x, c4.x);
        float h1 = fmaf(a4.y, hv.y, c4.y);
        float h2 = fmaf(a4.z, hv.z, c4.z);
        float h3 = fmaf(a4.w, hv.w, c4.w);
        if (doRelu) { h0 = fmaxf(h0, 0.f); h1 = fmaxf(h1, 0.f); h2 = fmaxf(h2, 0.f); h3 = fmaxf(h3, 0.f); }
        float m0 = fmaxf(h0 + e0.x + e1.x + e2.x, 0.f);
        float m1 = fmaxf(h1 + e0.y + e1.y + e2.y, 0.f);
        float m2 = fmaxf(h2 + e0.z + e1.z + e2.z, 0.f);
        float m3 = fmaxf(h3 + e0.w + e1.w + e2.w, 0.f);
        float* dstp = &g_agg[(size_t)dst * 64 + lane * 4];
        asm volatile("red.global.add.v4.f32 [%0], {%1,%2,%3,%4};"
                     :: "l"(dstp), "f"(m0), "f"(m1), "f"(m2), "f"(m3) : "memory");
    }
}

// ---------------- GEMM1: Y = Z @ W1 + b1, Z = (1+eps)*heff + agg; stats(Y) -------
// block tile: 128 rows x 128 cols, K=64. 256 threads, 8x8 micro-tile.
// dyn smem: Zs[64][128] + Ws[64][128] + ssum[128] + ssq[128]
#define GEMM1_SMEM ((64 * 128 + 64 * 128 + 256) * sizeof(float))
__global__ __launch_bounds__(256) void gemm1_kernel(int doRelu, const float* __restrict__ epsp,
                                                    const float* __restrict__ W1,
                                                    const float* __restrict__ bias1, int N) {
    extern __shared__ float sm[];
    float* Zs   = sm;                 // [k][m] 64x128
    float* Ws   = sm + 64 * 128;      // [k][n] 64x128
    float* ssum = Ws + 64 * 128;      // [128]
    float* ssq  = ssum + 128;         // [128]
    int tid = threadIdx.x;
    int rowBase = blockIdx.x * 128;
    float ope = 1.0f + *epsp;

    for (int t = tid; t < (64 * 128) / 4; t += 256)
        ((float4*)Ws)[t] = ((const float4*)W1)[t];

    for (int t = tid; t < 128 * 16; t += 256) {
        int r = t >> 4, kq = t & 15;
        int grow = rowBase + r;
        float4 hv, av;
        if (grow < N) {
            hv = ((const float4*)(g_h  + (size_t)grow * 64))[kq];
            av = ((const float4*)(g_agg + (size_t)grow * 64))[kq];
        } else {
            hv = make_float4(0.f, 0.f, 0.f, 0.f); av = hv;
        }
        float4 a4 = *(const float4*)(g_aff2 + kq * 4);
        float4 c4 = *(const float4*)(g_aff2 + 64 + kq * 4);
        float h0 = fmaf(a4.x, hv.x, c4.x), h1 = fmaf(a4.y, hv.y, c4.y);
        float h2 = fmaf(a4.z, hv.z, c4.z), h3 = fmaf(a4.w, hv.w, c4.w);
        if (doRelu) { h0 = fmaxf(h0, 0.f); h1 = fmaxf(h1, 0.f); h2 = fmaxf(h2, 0.f); h3 = fmaxf(h3, 0.f); }
        Zs[(kq * 4 + 0) * 128 + r] = fmaf(ope, h0, av.x);
        Zs[(kq * 4 + 1) * 128 + r] = fmaf(ope, h1, av.y);
        Zs[(kq * 4 + 2) * 128 + r] = fmaf(ope, h2, av.z);
        Zs[(kq * 4 + 3) * 128 + r] = fmaf(ope, h3, av.w);
    }
    if (tid < 128) { ssum[tid] = 0.f; ssq[tid] = 0.f; }
    __syncthreads();

    int tr = tid & 15, tc = tid >> 4;
    float acc[8][8];
#pragma unroll
    for (int i = 0; i < 8; i++)
#pragma unroll
        for (int j = 0; j < 8; j++) acc[i][j] = 0.f;

#pragma unroll 8
    for (int k = 0; k < 64; ++k) {
        float4 av0 = *(float4*)(Zs + k * 128 + tr * 8);
        float4 av1 = *(float4*)(Zs + k * 128 + tr * 8 + 4);
        float4 bv0 = *(float4*)(Ws + k * 128 + tc * 8);
        float4 bv1 = *(float4*)(Ws + k * 128 + tc * 8 + 4);
        float a[8] = {av0.x, av0.y, av0.z, av0.w, av1.x, av1.y, av1.z, av1.w};
        float b[8] = {bv0.x, bv0.y, bv0.z, bv0.w, bv1.x, bv1.y, bv1.z, bv1.w};
#pragma unroll
        for (int i = 0; i < 8; i++)
#pragma unroll
            for (int j = 0; j < 8; j++) acc[i][j] = fmaf(a[i], b[j], acc[i][j]);
    }

    float4 bb0 = *(const float4*)(bias1 + tc * 8);
    float4 bb1 = *(const float4*)(bias1 + tc * 8 + 4);
    float bj[8] = {bb0.x, bb0.y, bb0.z, bb0.w, bb1.x, bb1.y, bb1.z, bb1.w};
    float csum[8] = {0, 0, 0, 0, 0, 0, 0, 0}, csq[8] = {0, 0, 0, 0, 0, 0, 0, 0};
#pragma unroll
    for (int i = 0; i < 8; i++) {
        int grow = rowBase + tr * 8 + i;
        if (grow < N) {
            float y[8];
#pragma unroll
            for (int j = 0; j < 8; j++) {
                y[j] = acc[i][j] + bj[j];
                csum[j] += y[j];
                csq[j]  += y[j] * y[j];
            }
            float* yp = g_y + (size_t)grow * 128 + tc * 8;
            *(float4*)yp       = make_float4(y[0], y[1], y[2], y[3]);
            *(float4*)(yp + 4) = make_float4(y[4], y[5], y[6], y[7]);
        }
    }
#pragma unroll
    for (int j = 0; j < 8; j++) {
        atomicAdd(&ssum[tc * 8 + j], csum[j]);
        atomicAdd(&ssq [tc * 8 + j], csq[j]);
    }
    __syncthreads();
    if (tid < 128) {
        atomicAdd(&g_stats[tid],       ssum[tid]);
        atomicAdd(&g_stats[128 + tid], ssq[tid]);
    }
}

// ---------------- reduce1: stats -> BN1 affine (a1,c1) --------------------------
__global__ void reduce1_kernel(const float* __restrict__ gam, const float* __restrict__ bet, float invN) {
    int c = threadIdx.x;   // 128
    float s = g_stats[c], sq = g_stats[128 + c];
    float m = s * invN;
    float v = sq * invN - m * m;
    float r = rsqrtf(v + 1e-5f);
    float a = gam[c] * r;
    g_aff1[c]       = a;
    g_aff1[128 + c] = bet[c] - m * a;
}

// ---------------- GEMM2: T = relu(aff1(Y)) @ W2 + b2; stats(T); T -> g_h --------
// block tile: 128 rows x 64 cols, K=128 in 2 chunks of 64. 256 threads, 8x4 micro.
// dyn smem: Ys[64][128] + Ws2[64][64] + ssum[64] + ssq[64]
#define GEMM2_SMEM ((64 * 128 + 64 * 64 + 128) * sizeof(float))
__global__ __launch_bounds__(256) void gemm2_kernel(const float* __restrict__ W2,
                                                    const float* __restrict__ bias2, int N) {
    extern __shared__ float sm[];
    float* Ys   = sm;               // [k][m] 64x128 (per chunk)
    float* Ws2  = sm + 64 * 128;    // [k][n] 64x64
    float* ssum = Ws2 + 64 * 64;    // [64]
    float* ssq  = ssum + 64;        // [64]
    int tid = threadIdx.x;
    int rowBase = blockIdx.x * 128;
    int tr = tid & 15, tc = tid >> 4;

    if (tid < 64) { ssum[tid] = 0.f; ssq[tid] = 0.f; }

    float acc[8][4];
#pragma unroll
    for (int i = 0; i < 8; i++)
#pragma unroll
        for (int j = 0; j < 4; j++) acc[i][j] = 0.f;

#pragma unroll 1
    for (int kc = 0; kc < 2; ++kc) {
        if (kc) __syncthreads();   // protect smem reuse across chunks
        for (int t = tid; t < (64 * 64) / 4; t += 256)
            ((float4*)Ws2)[t] = ((const float4*)(W2 + kc * 64 * 64))[t];
        for (int t = tid; t < 128 * 16; t += 256) {
            int r = t >> 4, kq = t & 15;
            int grow = rowBase + r;
            float4 yv = (grow < N) ? ((const float4*)(g_y + (size_t)grow * 128))[kc * 16 + kq]
                                   : make_float4(0.f, 0.f, 0.f, 0.f);
            int kb = kc * 64 + kq * 4;
            float4 a4 = *(const float4*)(g_aff1 + kb);
            float4 c4 = *(const float4*)(g_aff1 + 128 + kb);
            Ys[(kq * 4 + 0) * 128 + r] = fmaxf(fmaf(a4.x, yv.x, c4.x), 0.f);
            Ys[(kq * 4 + 1) * 128 + r] = fmaxf(fmaf(a4.y, yv.y, c4.y), 0.f);
            Ys[(kq * 4 + 2) * 128 + r] = fmaxf(fmaf(a4.z, yv.z, c4.z), 0.f);
            Ys[(kq * 4 + 3) * 128 + r] = fmaxf(fmaf(a4.w, yv.w, c4.w), 0.f);
        }
        __syncthreads();
#pragma unroll 8
        for (int k = 0; k < 64; ++k) {
            float4 av0 = *(float4*)(Ys + k * 128 + tr * 8);
            float4 av1 = *(float4*)(Ys + k * 128 + tr * 8 + 4);
            float4 bv  = *(float4*)(Ws2 + k * 64 + tc * 4);
            float a[8] = {av0.x, av0.y, av0.z, av0.w, av1.x, av1.y, av1.z, av1.w};
            float b[4] = {bv.x, bv.y, bv.z, bv.w};
#pragma unroll
            for (int i = 0; i < 8; i++)
#pragma unroll
                for (int j = 0; j < 4; j++) acc[i][j] = fmaf(a[i], b[j], acc[i][j]);
        }
    }

    float4 bb = *(const float4*)(bias2 + tc * 4);
    float bj[4] = {bb.x, bb.y, bb.z, bb.w};
    float csum[4] = {0, 0, 0, 0}, csq[4] = {0, 0, 0, 0};
#pragma unroll
    for (int i = 0; i < 8; i++) {
        int grow = rowBase + tr * 8 + i;
        if (grow < N) {
            float tv[4];
#pragma unroll
            for (int j = 0; j < 4; j++) {
                tv[j] = acc[i][j] + bj[j];
                csum[j] += tv[j];
                csq[j]  += tv[j] * tv[j];
            }
            *(float4*)(g_h + (size_t)grow * 64 + tc * 4) = make_float4(tv[0], tv[1], tv[2], tv[3]);
        }
    }
#pragma unroll
    for (int j = 0; j < 4; j++) {
        atomicAdd(&ssum[tc * 4 + j], csum[j]);
        atomicAdd(&ssq [tc * 4 + j], csq[j]);
    }
    __syncthreads();
    if (tid < 64) {
        atomicAdd(&g_stats[256 + tid], ssum[tid]);
        atomicAdd(&g_stats[320 + tid], ssq[tid]);
    }
}

// ---------------- reduce2: stats -> outer BN affine (a2,c2) ---------------------
__global__ void reduce2_kernel(const float* __restrict__ gam, const float* __restrict__ bet, float invN) {
    int c = threadIdx.x;   // 64
    float s = g_stats[256 + c], sq = g_stats[320 + c];
    float m = s * invN;
    float v = sq * invN - m * m;
    float r = rsqrtf(v + 1e-5f);
    float a = gam[c] * r;
    g_aff2[c]      = a;
    g_aff2[64 + c] = bet[c] - m * a;
}

// ---------------- final: out = aff2(g_h) (no relu) ; append batch ---------------
__global__ void final_kernel(const int* __restrict__ batch, float* __restrict__ out,
                             int N, long long outn) {
    int t = blockIdx.x * blockDim.x + threadIdx.x;
    int node = t >> 4, lane = t & 15;
    if (node < N) {
        float4 a4 = *(const float4*)(g_aff2 + lane * 4);
        float4 c4 = *(const float4*)(g_aff2 + 64 + lane * 4);
        float4 tv = *(const float4*)(g_h + (size_t)node * 64 + lane * 4);
        float4 o;
        o.x = fmaf(a4.x, tv.x, c4.x);
        o.y = fmaf(a4.y, tv.y, c4.y);
        o.z = fmaf(a4.z, tv.z, c4.z);
        o.w = fmaf(a4.w, tv.w, c4.w);
        *(float4*)(out + (size_t)node * 64 + lane * 4) = o;
    }
    if (t < N && outn >= (long long)N * 64 + N)
        out[(size_t)N * 64 + t] = (float)batch[t];
}

// -------------------------------- host side ------------------------------------
extern "C" void kernel_launch(void* const* d_in, const int* in_sizes, int n_in,
                              void* d_out, int out_size) {
    const int*   x        = (const int*)d_in[0];
    const int*   ei       = (const int*)d_in[1];
    const int*   ea       = (const int*)d_in[2];
    const int*   batch    = (const int*)d_in[3];
    const float* atom_emb = (const float*)d_in[4];
    const float* bond_emb = (const float*)d_in[5];
    const float* eps      = (const float*)d_in[6];
    const float* W1       = (const float*)d_in[7];
    const float* b1       = (const float*)d_in[8];
    const float* bn1_g    = (const float*)d_in[9];
    const float* bn1_b    = (const float*)d_in[10];
    const float* W2       = (const float*)d_in[11];
    const float* b2       = (const float*)d_in[12];
    const float* bn_g     = (const float*)d_in[13];
    const float* bn_b     = (const float*)d_in[14];

    int N = in_sizes[0] / 9;
    int E = in_sizes[1] / 2;
    float invN = 1.0f / (float)N;

    // one-time host-side setup (symbol addresses / smem opt-in)
    static void* aggp = nullptr;
    static void* statsp = nullptr;
    if (!aggp) {
        cudaFuncSetAttribute(gemm1_kernel, cudaFuncAttributeMaxDynamicSharedMemorySize, (int)GEMM1_SMEM);
        cudaFuncSetAttribute(gemm2_kernel, cudaFuncAttributeMaxDynamicSharedMemorySize, (int)GEMM2_SMEM);
        cudaGetSymbolAddress(&aggp, g_agg);
        cudaGetSymbolAddress(&statsp, g_stats);
    }

    int nodeBlocks = (N * 16 + 255) / 256;
    int edgeBlocks = (E + EPB - 1) / EPB;
    int rowBlocks  = (N + 127) / 128;

    atom_kernel<<<nodeBlocks, 256>>>(x, atom_emb, N);
    init_aff_kernel<<<1, 128>>>();

    for (int l = 0; l < NLAYER; ++l) {
        cudaMemsetAsync(aggp, 0, (size_t)N * 64 * sizeof(float));
        cudaMemsetAsync(statsp, 0, 384 * sizeof(float));
        edge_kernel<<<edgeBlocks, 256>>>(ei, ea, bond_emb + (size_t)l * 3 * 8 * 64,
                                         (l > 0) ? 1 : 0, E, N);
        gemm1_kernel<<<rowBlocks, 256, GEMM1_SMEM>>>((l > 0) ? 1 : 0, eps + l,
                                                     W1 + (size_t)l * 64 * 128,
                                                     b1 + (size_t)l * 128, N);
        reduce1_kernel<<<1, 128>>>(bn1_g + (size_t)l * 128, bn1_b + (size_t)l * 128, invN);
        gemm2_kernel<<<rowBlocks, 256, GEMM2_SMEM>>>(W2 + (size_t)l * 128 * 64,
                                                     b2 + (size_t)l * 64, N);
        reduce2_kernel<<<1, 64>>>(bn_g + (size_t)l * 64, bn_b + (size_t)l * 64, invN);
    }

    final_kernel<<<nodeBlocks, 256>>>(batch, (float*)d_out, N, (long long)out_size);
}

// round 3
// speedup vs baseline: 1.0099x; 1.0099x over previous
#include <cuda_runtime.h>
#include <cuda_bf16.h>

#define EMB 64
#define MAXN 100000
#define MAXE 1000000
#define NLAYER 4

// ---------------- scratch (__device__ globals: allocation-free) ----------------
__device__ float g_h[(size_t)MAXN * 64];          // current node features (raw, pre-affine)
__device__ float g_agg[(size_t)MAXN * 64];        // scatter-add target
__device__ float g_y[(size_t)MAXN * 128];         // GEMM1 output
__device__ float g_stats[384];                    // [sum128, sq128, sum64, sq64]
__device__ float g_aff1[256];                     // BN1 affine: a[128], c[128]
__device__ float g_aff2[128];                     // outer BN affine: a[64], c[64]

// ---------------- f32x2 packed-FMA helpers (sm_103a) ----------------------------
__device__ __forceinline__ void ffma2(unsigned long long& d, unsigned long long a,
                                      unsigned long long b) {
    asm("fma.rn.f32x2 %0, %1, %2, %0;" : "+l"(d) : "l"(a), "l"(b));
}
__device__ __forceinline__ unsigned long long bcast2(float v) {
    unsigned long long r;
    asm("mov.b64 %0, {%1, %1};" : "=l"(r) : "f"(v));
    return r;
}
__device__ __forceinline__ float2 unpack2(unsigned long long v) {
    float2 r;
    asm("mov.b64 {%0, %1}, %2;" : "=f"(r.x), "=f"(r.y) : "l"(v));
    return r;
}

// ---------------- init affine to identity (for layer 0 consumers) --------------
__global__ void init_aff_kernel() {
    int t = threadIdx.x;
    if (t < 64) g_aff2[t] = 1.0f;
    else        g_aff2[t] = 0.0f;   // t in [64,128)
}

// ---------------- atom encoder: h[n] = sum_c atom_emb[c][x[n,c]] ----------------
__global__ void atom_kernel(const int* __restrict__ x, const float* __restrict__ aemb, int N) {
    int t = blockIdx.x * blockDim.x + threadIdx.x;
    int node = t >> 4, lane = t & 15;
    if (node >= N) return;
    float4 s = make_float4(0.f, 0.f, 0.f, 0.f);
#pragma unroll
    for (int c = 0; c < 9; c++) {
        int v = __ldg(&x[node * 9 + c]);
        float4 e = *(const float4*)&aemb[((size_t)(c * 64 + v)) * 64 + lane * 4];
        s.x += e.x; s.y += e.y; s.z += e.z; s.w += e.w;
    }
    *(float4*)&g_h[(size_t)node * 64 + lane * 4] = s;
}

// ---------------- edge kernel: agg[dst] += relu(heff[src] + ee) -----------------
#define EPB 128   // edges per block (16 groups x 8 iters)
__global__ __launch_bounds__(256) void edge_kernel(const int* __restrict__ ei, const int* __restrict__ ea,
                            const float* __restrict__ bt /* 3*8*64 for this layer */,
                            int doRelu, int E, int N) {
    __shared__ float sbt[3 * 8 * 64];
    __shared__ float sa[64], sc[64];
    int tid = threadIdx.x;
    for (int t = tid; t < 1536; t += 256) sbt[t] = bt[t];
    if (tid < 64) { sa[tid] = g_aff2[tid]; sc[tid] = g_aff2[64 + tid]; }
    __syncthreads();

    int lane = tid & 15, grp = tid >> 4;
    int base = blockIdx.x * EPB;
    float4 a4 = *(float4*)&sa[lane * 4];
    float4 c4 = *(float4*)&sc[lane * 4];

#pragma unroll 1
    for (int i = 0; i < EPB / 16; i++) {
        int e = base + i * 16 + grp;
        if (e >= E) break;
        int src = __ldg(&ei[e]);
        int dst = __ldg(&ei[E + e]);
        int b0 = __ldg(&ea[e * 3 + 0]);
        int b1 = __ldg(&ea[e * 3 + 1]);
        int b2 = __ldg(&ea[e * 3 + 2]);
        float4 e0 = *(float4*)&sbt[(0 * 8 + b0) * 64 + lane * 4];
        float4 e1 = *(float4*)&sbt[(1 * 8 + b1) * 64 + lane * 4];
        float4 e2 = *(float4*)&sbt[(2 * 8 + b2) * 64 + lane * 4];
        float4 hv = __ldg((const float4*)&g_h[(size_t)src * 64 + lane * 4]);
        // affine + optional relu (previous layer's BN folded)
        float h0 = fmaf(a4.x, hv.x, c4.x);
        float h1 = fmaf(a4.y, hv.y, c4.y);
        float h2 = fmaf(a4.z, hv.z, c4.z);
        float h3 = fmaf(a4.w, hv.w, c4.w);
        if (doRelu) { h0 = fmaxf(h0, 0.f); h1 = fmaxf(h1, 0.f); h2 = fmaxf(h2, 0.f); h3 = fmaxf(h3, 0.f); }
        float m0 = fmaxf(h0 + e0.x + e1.x + e2.x, 0.f);
        float m1 = fmaxf(h1 + e0.y + e1.y + e2.y, 0.f);
        float m2 = fmaxf(h2 + e0.z + e1.z + e2.z, 0.f);
        float m3 = fmaxf(h3 + e0.w + e1.w + e2.w, 0.f);
        float* dstp = &g_agg[(size_t)dst * 64 + lane * 4];
        asm volatile("red.global.add.v4.f32 [%0], {%1,%2,%3,%4};"
                     :: "l"(dstp), "f"(m0), "f"(m1), "f"(m2), "f"(m3) : "memory");
    }
}

// ---------------- GEMM1: Y = Z @ W1 + b1, Z = (1+eps)*heff + agg; stats(Y) -------
// block tile: 128 rows x 128 cols, K=64. 256 threads, 8x8 micro-tile (row pairs
// packed in f32x2 accumulators).
// dyn smem: Zs[64][128] + Ws[64][128] + ssum[128] + ssq[128]
#define GEMM1_SMEM ((64 * 128 + 64 * 128 + 256) * sizeof(float))
__global__ __launch_bounds__(256) void gemm1_kernel(int doRelu, const float* __restrict__ epsp,
                                                    const float* __restrict__ W1,
                                                    const float* __restrict__ bias1, int N) {
    extern __shared__ float sm[];
    float* Zs   = sm;                 // [k][m] 64x128
    float* Ws   = sm + 64 * 128;      // [k][n] 64x128
    float* ssum = Ws + 64 * 128;      // [128]
    float* ssq  = ssum + 128;         // [128]
    int tid = threadIdx.x;
    int rowBase = blockIdx.x * 128;
    float ope = 1.0f + *epsp;

    for (int t = tid; t < (64 * 128) / 4; t += 256)
        ((float4*)Ws)[t] = ((const float4*)W1)[t];

    for (int t = tid; t < 128 * 16; t += 256) {
        int r = t >> 4, kq = t & 15;
        int grow = rowBase + r;
        float4 hv, av;
        if (grow < N) {
            hv = ((const float4*)(g_h  + (size_t)grow * 64))[kq];
            av = ((const float4*)(g_agg + (size_t)grow * 64))[kq];
        } else {
            hv = make_float4(0.f, 0.f, 0.f, 0.f); av = hv;
        }
        float4 a4 = *(const float4*)(g_aff2 + kq * 4);
        float4 c4 = *(const float4*)(g_aff2 + 64 + kq * 4);
        float h0 = fmaf(a4.x, hv.x, c4.x), h1 = fmaf(a4.y, hv.y, c4.y);
        float h2 = fmaf(a4.z, hv.z, c4.z), h3 = fmaf(a4.w, hv.w, c4.w);
        if (doRelu) { h0 = fmaxf(h0, 0.f); h1 = fmaxf(h1, 0.f); h2 = fmaxf(h2, 0.f); h3 = fmaxf(h3, 0.f); }
        Zs[(kq * 4 + 0) * 128 + r] = fmaf(ope, h0, av.x);
        Zs[(kq * 4 + 1) * 128 + r] = fmaf(ope, h1, av.y);
        Zs[(kq * 4 + 2) * 128 + r] = fmaf(ope, h2, av.z);
        Zs[(kq * 4 + 3) * 128 + r] = fmaf(ope, h3, av.w);
    }
    if (tid < 128) { ssum[tid] = 0.f; ssq[tid] = 0.f; }
    __syncthreads();

    int tr = tid & 15, tc = tid >> 4;
    // acc2[ip][j]: rows (tr*8 + 2ip, tr*8 + 2ip + 1), col tc*8 + j
    unsigned long long acc2[4][8];
#pragma unroll
    for (int i = 0; i < 4; i++)
#pragma unroll
        for (int j = 0; j < 8; j++) acc2[i][j] = 0ull;

#pragma unroll 4
    for (int k = 0; k < 64; ++k) {
        // A: 4 packed row-pairs, straight from smem (128-bit loads)
        ulonglong2 a01 = *(ulonglong2*)(Zs + k * 128 + tr * 8);
        ulonglong2 a23 = *(ulonglong2*)(Zs + k * 128 + tr * 8 + 4);
        unsigned long long ap[4] = {a01.x, a01.y, a23.x, a23.y};
        // B: 8 scalar values, broadcast into pairs
        float4 bv0 = *(float4*)(Ws + k * 128 + tc * 8);
        float4 bv1 = *(float4*)(Ws + k * 128 + tc * 8 + 4);
        unsigned long long bb[8] = {bcast2(bv0.x), bcast2(bv0.y), bcast2(bv0.z), bcast2(bv0.w),
                                    bcast2(bv1.x), bcast2(bv1.y), bcast2(bv1.z), bcast2(bv1.w)};
#pragma unroll
        for (int i = 0; i < 4; i++)
#pragma unroll
            for (int j = 0; j < 8; j++) ffma2(acc2[i][j], ap[i], bb[j]);
    }

    float4 bb0 = *(const float4*)(bias1 + tc * 8);
    float4 bb1 = *(const float4*)(bias1 + tc * 8 + 4);
    float bj[8] = {bb0.x, bb0.y, bb0.z, bb0.w, bb1.x, bb1.y, bb1.z, bb1.w};
    float csum[8] = {0, 0, 0, 0, 0, 0, 0, 0}, csq[8] = {0, 0, 0, 0, 0, 0, 0, 0};
#pragma unroll
    for (int ip = 0; ip < 4; ip++) {
#pragma unroll
        for (int half = 0; half < 2; half++) {
            int grow = rowBase + tr * 8 + ip * 2 + half;
            if (grow < N) {
                float y[8];
#pragma unroll
                for (int j = 0; j < 8; j++) {
                    float2 p = unpack2(acc2[ip][j]);
                    float v = (half == 0 ? p.x : p.y) + bj[j];
                    y[j] = v;
                    csum[j] += v;
                    csq[j]  += v * v;
                }
                float* yp = g_y + (size_t)grow * 128 + tc * 8;
                *(float4*)yp       = make_float4(y[0], y[1], y[2], y[3]);
                *(float4*)(yp + 4) = make_float4(y[4], y[5], y[6], y[7]);
            }
        }
    }
#pragma unroll
    for (int j = 0; j < 8; j++) {
        atomicAdd(&ssum[tc * 8 + j], csum[j]);
        atomicAdd(&ssq [tc * 8 + j], csq[j]);
    }
    __syncthreads();
    if (tid < 128) {
        atomicAdd(&g_stats[tid],       ssum[tid]);
        atomicAdd(&g_stats[128 + tid], ssq[tid]);
    }
}

// ---------------- reduce1: stats -> BN1 affine (a1,c1) --------------------------
__global__ void reduce1_kernel(const float* __restrict__ gam, const float* __restrict__ bet, float invN) {
    int c = threadIdx.x;   // 128
    float s = g_stats[c], sq = g_stats[128 + c];
    float m = s * invN;
    float v = sq * invN - m * m;
    float r = rsqrtf(v + 1e-5f);
    float a = gam[c] * r;
    g_aff1[c]       = a;
    g_aff1[128 + c] = bet[c] - m * a;
}

// ---------------- GEMM2: T = relu(aff1(Y)) @ W2 + b2; stats(T); T -> g_h --------
// block tile: 128 rows x 64 cols, K=128 in 2 chunks of 64. 256 threads, 8x4 micro
// (row pairs packed in f32x2 accumulators).
// dyn smem: Ys[64][128] + Ws2[64][64] + ssum[64] + ssq[64]
#define GEMM2_SMEM ((64 * 128 + 64 * 64 + 128) * sizeof(float))
__global__ __launch_bounds__(256) void gemm2_kernel(const float* __restrict__ W2,
                                                    const float* __restrict__ bias2, int N) {
    extern __shared__ float sm[];
    float* Ys   = sm;               // [k][m] 64x128 (per chunk)
    float* Ws2  = sm + 64 * 128;    // [k][n] 64x64
    float* ssum = Ws2 + 64 * 64;    // [64]
    float* ssq  = ssum + 64;        // [64]
    int tid = threadIdx.x;
    int rowBase = blockIdx.x * 128;
    int tr = tid & 15, tc = tid >> 4;

    if (tid < 64) { ssum[tid] = 0.f; ssq[tid] = 0.f; }

    // acc2[ip][j]: rows (tr*8 + 2ip, tr*8 + 2ip + 1), col tc*4 + j
    unsigned long long acc2[4][4];
#pragma unroll
    for (int i = 0; i < 4; i++)
#pragma unroll
        for (int j = 0; j < 4; j++) acc2[i][j] = 0ull;

#pragma unroll 1
    for (int kc = 0; kc < 2; ++kc) {
        if (kc) __syncthreads();   // protect smem reuse across chunks
        for (int t = tid; t < (64 * 64) / 4; t += 256)
            ((float4*)Ws2)[t] = ((const float4*)(W2 + kc * 64 * 64))[t];
        for (int t = tid; t < 128 * 16; t += 256) {
            int r = t >> 4, kq = t & 15;
            int grow = rowBase + r;
            float4 yv = (grow < N) ? ((const float4*)(g_y + (size_t)grow * 128))[kc * 16 + kq]
                                   : make_float4(0.f, 0.f, 0.f, 0.f);
            int kb = kc * 64 + kq * 4;
            float4 a4 = *(const float4*)(g_aff1 + kb);
            float4 c4 = *(const float4*)(g_aff1 + 128 + kb);
            Ys[(kq * 4 + 0) * 128 + r] = fmaxf(fmaf(a4.x, yv.x, c4.x), 0.f);
            Ys[(kq * 4 + 1) * 128 + r] = fmaxf(fmaf(a4.y, yv.y, c4.y), 0.f);
            Ys[(kq * 4 + 2) * 128 + r] = fmaxf(fmaf(a4.z, yv.z, c4.z), 0.f);
            Ys[(kq * 4 + 3) * 128 + r] = fmaxf(fmaf(a4.w, yv.w, c4.w), 0.f);
        }
        __syncthreads();
#pragma unroll 4
        for (int k = 0; k < 64; ++k) {
            ulonglong2 a01 = *(ulonglong2*)(Ys + k * 128 + tr * 8);
            ulonglong2 a23 = *(ulonglong2*)(Ys + k * 128 + tr * 8 + 4);
            unsigned long long ap[4] = {a01.x, a01.y, a23.x, a23.y};
            float4 bv = *(float4*)(Ws2 + k * 64 + tc * 4);
            unsigned long long bb[4] = {bcast2(bv.x), bcast2(bv.y), bcast2(bv.z), bcast2(bv.w)};
#pragma unroll
            for (int i = 0; i < 4; i++)
#pragma unroll
                for (int j = 0; j < 4; j++) ffma2(acc2[i][j], ap[i], bb[j]);
        }
    }

    float4 bbv = *(const float4*)(bias2 + tc * 4);
    float bj[4] = {bbv.x, bbv.y, bbv.z, bbv.w};
    float csum[4] = {0, 0, 0, 0}, csq[4] = {0, 0, 0, 0};
#pragma unroll
    for (int ip = 0; ip < 4; ip++) {
#pragma unroll
        for (int half = 0; half < 2; half++) {
            int grow = rowBase + tr * 8 + ip * 2 + half;
            if (grow < N) {
                float tv[4];
#pragma unroll
                for (int j = 0; j < 4; j++) {
                    float2 p = unpack2(acc2[ip][j]);
                    float v = (half == 0 ? p.x : p.y) + bj[j];
                    tv[j] = v;
                    csum[j] += v;
                    csq[j]  += v * v;
                }
                *(float4*)(g_h + (size_t)grow * 64 + tc * 4) = make_float4(tv[0], tv[1], tv[2], tv[3]);
            }
        }
    }
#pragma unroll
    for (int j = 0; j < 4; j++) {
        atomicAdd(&ssum[tc * 4 + j], csum[j]);
        atomicAdd(&ssq [tc * 4 + j], csq[j]);
    }
    __syncthreads();
    if (tid < 64) {
        atomicAdd(&g_stats[256 + tid], ssum[tid]);
        atomicAdd(&g_stats[320 + tid], ssq[tid]);
    }
}

// ---------------- reduce2: stats -> outer BN affine (a2,c2) ---------------------
__global__ void reduce2_kernel(const float* __restrict__ gam, const float* __restrict__ bet, float invN) {
    int c = threadIdx.x;   // 64
    float s = g_stats[256 + c], sq = g_stats[320 + c];
    float m = s * invN;
    float v = sq * invN - m * m;
    float r = rsqrtf(v + 1e-5f);
    float a = gam[c] * r;
    g_aff2[c]      = a;
    g_aff2[64 + c] = bet[c] - m * a;
}

// ---------------- final: out = aff2(g_h) (no relu) ; append batch ---------------
__global__ void final_kernel(const int* __restrict__ batch, float* __restrict__ out,
                             int N, long long outn) {
    int t = blockIdx.x * blockDim.x + threadIdx.x;
    int node = t >> 4, lane = t & 15;
    if (node < N) {
        float4 a4 = *(const float4*)(g_aff2 + lane * 4);
        float4 c4 = *(const float4*)(g_aff2 + 64 + lane * 4);
        float4 tv = *(const float4*)(g_h + (size_t)node * 64 + lane * 4);
        float4 o;
        o.x = fmaf(a4.x, tv.x, c4.x);
        o.y = fmaf(a4.y, tv.y, c4.y);
        o.z = fmaf(a4.z, tv.z, c4.z);
        o.w = fmaf(a4.w, tv.w, c4.w);
        *(float4*)(out + (size_t)node * 64 + lane * 4) = o;
    }
    if (t < N && outn >= (long long)N * 64 + N)
        out[(size_t)N * 64 + t] = (float)batch[t];
}

// -------------------------------- host side ------------------------------------
extern "C" void kernel_launch(void* const* d_in, const int* in_sizes, int n_in,
                              void* d_out, int out_size) {
    const int*   x        = (const int*)d_in[0];
    const int*   ei       = (const int*)d_in[1];
    const int*   ea       = (const int*)d_in[2];
    const int*   batch    = (const int*)d_in[3];
    const float* atom_emb = (const float*)d_in[4];
    const float* bond_emb = (const float*)d_in[5];
    const float* eps      = (const float*)d_in[6];
    const float* W1       = (const float*)d_in[7];
    const float* b1       = (const float*)d_in[8];
    const float* bn1_g    = (const float*)d_in[9];
    const float* bn1_b    = (const float*)d_in[10];
    const float* W2       = (const float*)d_in[11];
    const float* b2       = (const float*)d_in[12];
    const float* bn_g     = (const float*)d_in[13];
    const float* bn_b     = (const float*)d_in[14];

    int N = in_sizes[0] / 9;
    int E = in_sizes[1] / 2;
    float invN = 1.0f / (float)N;

    // one-time host-side setup (symbol addresses / smem opt-in)
    static void* aggp = nullptr;
    static void* statsp = nullptr;
    if (!aggp) {
        cudaFuncSetAttribute(gemm1_kernel, cudaFuncAttributeMaxDynamicSharedMemorySize, (int)GEMM1_SMEM);
        cudaFuncSetAttribute(gemm2_kernel, cudaFuncAttributeMaxDynamicSharedMemorySize, (int)GEMM2_SMEM);
        cudaGetSymbolAddress(&aggp, g_agg);
        cudaGetSymbolAddress(&statsp, g_stats);
    }

    int nodeBlocks = (N * 16 + 255) / 256;
    int edgeBlocks = (E + EPB - 1) / EPB;
    int rowBlocks  = (N + 127) / 128;

    atom_kernel<<<nodeBlocks, 256>>>(x, atom_emb, N);
    init_aff_kernel<<<1, 128>>>();

    for (int l = 0; l < NLAYER; ++l) {
        cudaMemsetAsync(aggp, 0, (size_t)N * 64 * sizeof(float));
        cudaMemsetAsync(statsp, 0, 384 * sizeof(float));
        edge_kernel<<<edgeBlocks, 256>>>(ei, ea, bond_emb + (size_t)l * 3 * 8 * 64,
                                         (l > 0) ? 1 : 0, E, N);
        gemm1_kernel<<<rowBlocks, 256, GEMM1_SMEM>>>((l > 0) ? 1 : 0, eps + l,
                                                     W1 + (size_t)l * 64 * 128,
                                                     b1 + (size_t)l * 128, N);
        reduce1_kernel<<<1, 128>>>(bn1_g + (size_t)l * 128, bn1_b + (size_t)l * 128, invN);
        gemm2_kernel<<<rowBlocks, 256, GEMM2_SMEM>>>(W2 + (size_t)l * 128 * 64,
                                                     b2 + (size_t)l * 64, N);
        reduce2_kernel<<<1, 64>>>(bn_g + (size_t)l * 64, bn_b + (size_t)l * 64, invN);
    }

    final_kernel<<<nodeBlocks, 256>>>(batch, (float*)d_out, N, (long long)out_size);
}

// round 6
// speedup vs baseline: 1.2692x; 1.2568x over previous
#include <cuda_runtime.h>
#include <cuda_bf16.h>

#define EMB 64
#define MAXN 100000
#define MAXE 1000000
#define NLAYER 4

// ---------------- scratch (__device__ globals: allocation-free) ----------------
__device__ float g_h[(size_t)MAXN * 64];          // current node features (raw, pre-affine)
__device__ float g_agg[(size_t)MAXN * 64];        // scatter-add target
__device__ float g_y[(size_t)MAXN * 128];         // GEMM1 output
__device__ float g_stats[384];                    // [sum128, sq128, sum64, sq64]
__device__ float g_aff1[256];                     // BN1 affine: a[128], c[128]
__device__ float g_aff2[128];                     // outer BN affine: a[64], c[64]

// ---------------- f32x2 packed-FMA helpers (sm_103a) ----------------------------
__device__ __forceinline__ void ffma2(unsigned long long& d, unsigned long long a,
                                      unsigned long long b) {
    asm("fma.rn.f32x2 %0, %1, %2, %0;" : "+l"(d) : "l"(a), "l"(b));
}
__device__ __forceinline__ unsigned long long bcast2(float v) {
    unsigned long long r;
    asm("mov.b64 %0, {%1, %1};" : "=l"(r) : "f"(v));
    return r;
}
__device__ __forceinline__ float2 unpack2(unsigned long long v) {
    float2 r;
    asm("mov.b64 {%0, %1}, %2;" : "=f"(r.x), "=f"(r.y) : "l"(v));
    return r;
}
__device__ __forceinline__ float warp_sum(float v) {
#pragma unroll
    for (int o = 16; o > 0; o >>= 1) v += __shfl_xor_sync(0xffffffffu, v, o);
    return v;
}

// ---------------- init affine to identity (for layer 0 consumers) --------------
__global__ void init_aff_kernel() {
    int t = threadIdx.x;
    if (t < 64) g_aff2[t] = 1.0f;
    else        g_aff2[t] = 0.0f;   // t in [64,128)
}

// ---------------- atom encoder: h[n] = sum_c atom_emb[c][x[n,c]] ----------------
__global__ void atom_kernel(const int* __restrict__ x, const float* __restrict__ aemb, int N) {
    int t = blockIdx.x * blockDim.x + threadIdx.x;
    int node = t >> 4, lane = t & 15;
    if (node >= N) return;
    float4 s = make_float4(0.f, 0.f, 0.f, 0.f);
#pragma unroll
    for (int c = 0; c < 9; c++) {
        int v = __ldg(&x[node * 9 + c]);
        float4 e = *(const float4*)&aemb[((size_t)(c * 64 + v)) * 64 + lane * 4];
        s.x += e.x; s.y += e.y; s.z += e.z; s.w += e.w;
    }
    *(float4*)&g_h[(size_t)node * 64 + lane * 4] = s;
}

// ---------------- edge kernel: agg[dst] += relu(heff[src] + ee) -----------------
#define EPB 128   // edges per block (16 groups x 8 iters)
__global__ __launch_bounds__(256) void edge_kernel(const int* __restrict__ ei, const int* __restrict__ ea,
                            const float* __restrict__ bt /* 3*8*64 for this layer */,
                            int doRelu, int E, int N) {
    __shared__ float sbt[3 * 8 * 64];
    __shared__ float sa[64], sc[64];
    int tid = threadIdx.x;
    for (int t = tid; t < 1536; t += 256) sbt[t] = bt[t];
    if (tid < 64) { sa[tid] = g_aff2[tid]; sc[tid] = g_aff2[64 + tid]; }
    __syncthreads();

    int lane = tid & 15, grp = tid >> 4;
    int base = blockIdx.x * EPB;
    float4 a4 = *(float4*)&sa[lane * 4];
    float4 c4 = *(float4*)&sc[lane * 4];

#pragma unroll 1
    for (int i = 0; i < EPB / 16; i++) {
        int e = base + i * 16 + grp;
        if (e >= E) break;
        int src = __ldg(&ei[e]);
        int dst = __ldg(&ei[E + e]);
        int b0 = __ldg(&ea[e * 3 + 0]);
        int b1 = __ldg(&ea[e * 3 + 1]);
        int b2 = __ldg(&ea[e * 3 + 2]);
        float4 e0 = *(float4*)&sbt[(0 * 8 + b0) * 64 + lane * 4];
        float4 e1 = *(float4*)&sbt[(1 * 8 + b1) * 64 + lane * 4];
        float4 e2 = *(float4*)&sbt[(2 * 8 + b2) * 64 + lane * 4];
        float4 hv = __ldg((const float4*)&g_h[(size_t)src * 64 + lane * 4]);
        // affine + optional relu (previous layer's BN folded)
        float h0 = fmaf(a4.x, hv.x, c4.x);
        float h1 = fmaf(a4.y, hv.y, c4.y);
        float h2 = fmaf(a4.z, hv.z, c4.z);
        float h3 = fmaf(a4.w, hv.w, c4.w);
        if (doRelu) { h0 = fmaxf(h0, 0.f); h1 = fmaxf(h1, 0.f); h2 = fmaxf(h2, 0.f); h3 = fmaxf(h3, 0.f); }
        float m0 = fmaxf(h0 + e0.x + e1.x + e2.x, 0.f);
        float m1 = fmaxf(h1 + e0.y + e1.y + e2.y, 0.f);
        float m2 = fmaxf(h2 + e0.z + e1.z + e2.z, 0.f);
        float m3 = fmaxf(h3 + e0.w + e1.w + e2.w, 0.f);
        float* dstp = &g_agg[(size_t)dst * 64 + lane * 4];
        asm volatile("red.global.add.v4.f32 [%0], {%1,%2,%3,%4};"
                     :: "l"(dstp), "f"(m0), "f"(m1), "f"(m2), "f"(m3) : "memory");
    }
}

// ---------------- GEMM1: Y = Z @ W1 + b1, Z = (1+eps)*heff + agg; stats(Y) -------
// block tile: 128 rows x 128 cols, K=64. 512 threads, micro 4 rows x 8 cols.
// Warp layout: tr = tid&31 (row group), tc = tid>>5 (col group) -> whole warp
// shares tc => B smem loads are broadcast; A loads are conflict-free.
// dyn smem: Zs[64][128] + Ws[64][128] + ssum[128] + ssq[128]
#define GEMM1_SMEM ((64 * 128 + 64 * 128 + 256) * sizeof(float))
__global__ __launch_bounds__(512, 2) void gemm1_kernel(int doRelu, const float* __restrict__ epsp,
                                                       const float* __restrict__ W1,
                                                       const float* __restrict__ bias1, int N) {
    extern __shared__ float sm[];
    float* Zs   = sm;                 // [k][m] 64x128
    float* Ws   = sm + 64 * 128;      // [k][n] 64x128
    float* ssum = Ws + 64 * 128;      // [128]
    float* ssq  = ssum + 128;         // [128]
    int tid = threadIdx.x;
    int rowBase = blockIdx.x * 128;
    float ope = 1.0f + *epsp;

    for (int t = tid; t < (64 * 128) / 4; t += 512)
        ((float4*)Ws)[t] = ((const float4*)W1)[t];

    for (int t = tid; t < 128 * 16; t += 512) {
        int r = t >> 4, kq = t & 15;
        int grow = rowBase + r;
        float4 hv, av;
        if (grow < N) {
            hv = ((const float4*)(g_h  + (size_t)grow * 64))[kq];
            av = ((const float4*)(g_agg + (size_t)grow * 64))[kq];
        } else {
            hv = make_float4(0.f, 0.f, 0.f, 0.f); av = hv;
        }
        float4 a4 = *(const float4*)(g_aff2 + kq * 4);
        float4 c4 = *(const float4*)(g_aff2 + 64 + kq * 4);
        float h0 = fmaf(a4.x, hv.x, c4.x), h1 = fmaf(a4.y, hv.y, c4.y);
        float h2 = fmaf(a4.z, hv.z, c4.z), h3 = fmaf(a4.w, hv.w, c4.w);
        if (doRelu) { h0 = fmaxf(h0, 0.f); h1 = fmaxf(h1, 0.f); h2 = fmaxf(h2, 0.f); h3 = fmaxf(h3, 0.f); }
        Zs[(kq * 4 + 0) * 128 + r] = fmaf(ope, h0, av.x);
        Zs[(kq * 4 + 1) * 128 + r] = fmaf(ope, h1, av.y);
        Zs[(kq * 4 + 2) * 128 + r] = fmaf(ope, h2, av.z);
        Zs[(kq * 4 + 3) * 128 + r] = fmaf(ope, h3, av.w);
    }
    if (tid < 128) { ssum[tid] = 0.f; ssq[tid] = 0.f; }
    __syncthreads();

    int tr = tid & 31;   // rows tr*4 .. tr*4+3
    int tc = tid >> 5;   // cols tc*8 .. tc*8+7 (whole warp shares tc)
    // acc2[ip][j]: rows (tr*4 + 2ip, tr*4 + 2ip + 1), col tc*8 + j
    unsigned long long acc2[2][8];
#pragma unroll
    for (int i = 0; i < 2; i++)
#pragma unroll
        for (int j = 0; j < 8; j++) acc2[i][j] = 0ull;

#pragma unroll 4
    for (int k = 0; k < 64; ++k) {
        ulonglong2 ap = *(ulonglong2*)(Zs + k * 128 + tr * 4);   // 2 row-pairs
        float4 bv0 = *(float4*)(Ws + k * 128 + tc * 8);          // broadcast
        float4 bv1 = *(float4*)(Ws + k * 128 + tc * 8 + 4);      // broadcast
        {
            unsigned long long b0 = bcast2(bv0.x), b1 = bcast2(bv0.y),
                               b2 = bcast2(bv0.z), b3 = bcast2(bv0.w);
            ffma2(acc2[0][0], ap.x, b0); ffma2(acc2[1][0], ap.y, b0);
            ffma2(acc2[0][1], ap.x, b1); ffma2(acc2[1][1], ap.y, b1);
            ffma2(acc2[0][2], ap.x, b2); ffma2(acc2[1][2], ap.y, b2);
            ffma2(acc2[0][3], ap.x, b3); ffma2(acc2[1][3], ap.y, b3);
        }
        {
            unsigned long long b4 = bcast2(bv1.x), b5 = bcast2(bv1.y),
                               b6 = bcast2(bv1.z), b7 = bcast2(bv1.w);
            ffma2(acc2[0][4], ap.x, b4); ffma2(acc2[1][4], ap.y, b4);
            ffma2(acc2[0][5], ap.x, b5); ffma2(acc2[1][5], ap.y, b5);
            ffma2(acc2[0][6], ap.x, b6); ffma2(acc2[1][6], ap.y, b6);
            ffma2(acc2[0][7], ap.x, b7); ffma2(acc2[1][7], ap.y, b7);
        }
    }

    float4 bb0 = *(const float4*)(bias1 + tc * 8);
    float4 bb1 = *(const float4*)(bias1 + tc * 8 + 4);
    float bj[8] = {bb0.x, bb0.y, bb0.z, bb0.w, bb1.x, bb1.y, bb1.z, bb1.w};
    float csum[8] = {0, 0, 0, 0, 0, 0, 0, 0}, csq[8] = {0, 0, 0, 0, 0, 0, 0, 0};
#pragma unroll
    for (int ip = 0; ip < 2; ip++) {
#pragma unroll
        for (int half = 0; half < 2; half++) {
            int grow = rowBase + tr * 4 + ip * 2 + half;
            if (grow < N) {
                float y[8];
#pragma unroll
                for (int j = 0; j < 8; j++) {
                    float2 p = unpack2(acc2[ip][j]);
                    float v = (half == 0 ? p.x : p.y) + bj[j];
                    y[j] = v;
                    csum[j] += v;
                    csq[j]  += v * v;
                }
                float* yp = g_y + (size_t)grow * 128 + tc * 8;
                *(float4*)yp       = make_float4(y[0], y[1], y[2], y[3]);
                *(float4*)(yp + 4) = make_float4(y[4], y[5], y[6], y[7]);
            }
        }
    }
    // warp-level reduce (all lanes share tc), then one atomic per column per warp
#pragma unroll
    for (int j = 0; j < 8; j++) {
        float s = warp_sum(csum[j]);
        float q = warp_sum(csq[j]);
        if ((tid & 31) == 0) {
            atomicAdd(&ssum[tc * 8 + j], s);
            atomicAdd(&ssq [tc * 8 + j], q);
        }
    }
    __syncthreads();
    if (tid < 128) {
        atomicAdd(&g_stats[tid],       ssum[tid]);
        atomicAdd(&g_stats[128 + tid], ssq[tid]);
    }
}

// ---------------- reduce1: stats -> BN1 affine (a1,c1) --------------------------
__global__ void reduce1_kernel(const float* __restrict__ gam, const float* __restrict__ bet, float invN) {
    int c = threadIdx.x;   // 128
    float s = g_stats[c], sq = g_stats[128 + c];
    float m = s * invN;
    float v = sq * invN - m * m;
    float r = rsqrtf(v + 1e-5f);
    float a = gam[c] * r;
    g_aff1[c]       = a;
    g_aff1[128 + c] = bet[c] - m * a;
}

// ---------------- GEMM2: T = relu(aff1(Y)) @ W2 + b2; stats(T); T -> g_h --------
// block tile: 128 rows x 64 cols, K=128 in 2 chunks of 64. 512 threads,
// micro 4 rows x 4 cols. Warp shares tc => B broadcast.
// dyn smem: Ys[64][128] + Ws2[64][64] + ssum[64] + ssq[64]
#define GEMM2_SMEM ((64 * 128 + 64 * 64 + 128) * sizeof(float))
__global__ __launch_bounds__(512, 2) void gemm2_kernel(const float* __restrict__ W2,
                                                       const float* __restrict__ bias2, int N) {
    extern __shared__ float sm[];
    float* Ys   = sm;               // [k][m] 64x128 (per chunk)
    float* Ws2  = sm + 64 * 128;    // [k][n] 64x64
    float* ssum = Ws2 + 64 * 64;    // [64]
    float* ssq  = ssum + 64;        // [64]
    int tid = threadIdx.x;
    int rowBase = blockIdx.x * 128;
    int tr = tid & 31;   // rows tr*4 .. +3
    int tc = tid >> 5;   // cols tc*4 .. +3

    if (tid < 64) { ssum[tid] = 0.f; ssq[tid] = 0.f; }

    // acc2[ip][j]: rows (tr*4 + 2ip, tr*4 + 2ip + 1), col tc*4 + j
    unsigned long long acc2[2][4];
#pragma unroll
    for (int i = 0; i < 2; i++)
#pragma unroll
        for (int j = 0; j < 4; j++) acc2[i][j] = 0ull;

#pragma unroll 1
    for (int kc = 0; kc < 2; ++kc) {
        if (kc) __syncthreads();   // protect smem reuse across chunks
        for (int t = tid; t < (64 * 64) / 4; t += 512)
            ((float4*)Ws2)[t] = ((const float4*)(W2 + kc * 64 * 64))[t];
        for (int t = tid; t < 128 * 16; t += 512) {
            int r = t >> 4, kq = t & 15;
            int grow = rowBase + r;
            float4 yv = (grow < N) ? ((const float4*)(g_y + (size_t)grow * 128))[kc * 16 + kq]
                                   : make_float4(0.f, 0.f, 0.f, 0.f);
            int kb = kc * 64 + kq * 4;
            float4 a4 = *(const float4*)(g_aff1 + kb);
            float4 c4 = *(const float4*)(g_aff1 + 128 + kb);
            Ys[(kq * 4 + 0) * 128 + r] = fmaxf(fmaf(a4.x, yv.x, c4.x), 0.f);
            Ys[(kq * 4 + 1) * 128 + r] = fmaxf(fmaf(a4.y, yv.y, c4.y), 0.f);
            Ys[(kq * 4 + 2) * 128 + r] = fmaxf(fmaf(a4.z, yv.z, c4.z), 0.f);
            Ys[(kq * 4 + 3) * 128 + r] = fmaxf(fmaf(a4.w, yv.w, c4.w), 0.f);
        }
        __syncthreads();
#pragma unroll 4
        for (int k = 0; k < 64; ++k) {
            ulonglong2 ap = *(ulonglong2*)(Ys + k * 128 + tr * 4);
            float4 bv = *(float4*)(Ws2 + k * 64 + tc * 4);   // broadcast
            unsigned long long b0 = bcast2(bv.x), b1 = bcast2(bv.y),
                               b2 = bcast2(bv.z), b3 = bcast2(bv.w);
            ffma2(acc2[0][0], ap.x, b0); ffma2(acc2[1][0], ap.y, b0);
            ffma2(acc2[0][1], ap.x, b1); ffma2(acc2[1][1], ap.y, b1);
            ffma2(acc2[0][2], ap.x, b2); ffma2(acc2[1][2], ap.y, b2);
            ffma2(acc2[0][3], ap.x, b3); ffma2(acc2[1][3], ap.y, b3);
        }
    }

    float4 bbv = *(const float4*)(bias2 + tc * 4);
    float bj[4] = {bbv.x, bbv.y, bbv.z, bbv.w};
    float csum[4] = {0, 0, 0, 0}, csq[4] = {0, 0, 0, 0};
#pragma unroll
    for (int ip = 0; ip < 2; ip++) {
#pragma unroll
        for (int half = 0; half < 2; half++) {
            int grow = rowBase + tr * 4 + ip * 2 + half;
            if (grow < N) {
                float tv[4];
#pragma unroll
                for (int j = 0; j < 4; j++) {
                    float2 p = unpack2(acc2[ip][j]);
                    float v = (half == 0 ? p.x : p.y) + bj[j];
                    tv[j] = v;
                    csum[j] += v;
                    csq[j]  += v * v;
                }
                *(float4*)(g_h + (size_t)grow * 64 + tc * 4) = make_float4(tv[0], tv[1], tv[2], tv[3]);
            }
        }
    }
#pragma unroll
    for (int j = 0; j < 4; j++) {
        float s = warp_sum(csum[j]);
        float q = warp_sum(csq[j]);
        if ((tid & 31) == 0) {
            atomicAdd(&ssum[tc * 4 + j], s);
            atomicAdd(&ssq [tc * 4 + j], q);
        }
    }
    __syncthreads();
    if (tid < 64) {
        atomicAdd(&g_stats[256 + tid], ssum[tid]);
        atomicAdd(&g_stats[320 + tid], ssq[tid]);
    }
}

// ---------------- reduce2: stats -> outer BN affine (a2,c2) ---------------------
__global__ void reduce2_kernel(const float* __restrict__ gam, const float* __restrict__ bet, float invN) {
    int c = threadIdx.x;   // 64
    float s = g_stats[256 + c], sq = g_stats[320 + c];
    float m = s * invN;
    float v = sq * invN - m * m;
    float r = rsqrtf(v + 1e-5f);
    float a = gam[c] * r;
    g_aff2[c]      = a;
    g_aff2[64 + c] = bet[c] - m * a;
}

// ---------------- final: out = aff2(g_h) (no relu) ; append batch ---------------
__global__ void final_kernel(const int* __restrict__ batch, float* __restrict__ out,
                             int N, long long outn) {
    int t = blockIdx.x * blockDim.x + threadIdx.x;
    int node = t >> 4, lane = t & 15;
    if (node < N) {
        float4 a4 = *(const float4*)(g_aff2 + lane * 4);
        float4 c4 = *(const float4*)(g_aff2 + 64 + lane * 4);
        float4 tv = *(const float4*)(g_h + (size_t)node * 64 + lane * 4);
        float4 o;
        o.x = fmaf(a4.x, tv.x, c4.x);
        o.y = fmaf(a4.y, tv.y, c4.y);
        o.z = fmaf(a4.z, tv.z, c4.z);
        o.w = fmaf(a4.w, tv.w, c4.w);
        *(float4*)(out + (size_t)node * 64 + lane * 4) = o;
    }
    if (t < N && outn >= (long long)N * 64 + N)
        out[(size_t)N * 64 + t] = (float)batch[t];
}

// -------------------------------- host side ------------------------------------
extern "C" void kernel_launch(void* const* d_in, const int* in_sizes, int n_in,
                              void* d_out, int out_size) {
    const int*   x        = (const int*)d_in[0];
    const int*   ei       = (const int*)d_in[1];
    const int*   ea       = (const int*)d_in[2];
    const int*   batch    = (const int*)d_in[3];
    const float* atom_emb = (const float*)d_in[4];
    const float* bond_emb = (const float*)d_in[5];
    const float* eps      = (const float*)d_in[6];
    const float* W1       = (const float*)d_in[7];
    const float* b1       = (const float*)d_in[8];
    const float* bn1_g    = (const float*)d_in[9];
    const float* bn1_b    = (const float*)d_in[10];
    const float* W2       = (const float*)d_in[11];
    const float* b2       = (const float*)d_in[12];
    const float* bn_g     = (const float*)d_in[13];
    const float* bn_b     = (const float*)d_in[14];

    int N = in_sizes[0] / 9;
    int E = in_sizes[1] / 2;
    float invN = 1.0f / (float)N;

    // one-time host-side setup (symbol addresses / smem opt-in)
    static void* aggp = nullptr;
    static void* statsp = nullptr;
    if (!aggp) {
        cudaFuncSetAttribute(gemm1_kernel, cudaFuncAttributeMaxDynamicSharedMemorySize, (int)GEMM1_SMEM);
        cudaFuncSetAttribute(gemm2_kernel, cudaFuncAttributeMaxDynamicSharedMemorySize, (int)GEMM2_SMEM);
        cudaGetSymbolAddress(&aggp, g_agg);
        cudaGetSymbolAddress(&statsp, g_stats);
    }

    int nodeBlocks = (N * 16 + 255) / 256;
    int edgeBlocks = (E + EPB - 1) / EPB;
    int rowBlocks  = (N + 127) / 128;

    atom_kernel<<<nodeBlocks, 256>>>(x, atom_emb, N);
    init_aff_kernel<<<1, 128>>>();

    for (int l = 0; l < NLAYER; ++l) {
        cudaMemsetAsync(aggp, 0, (size_t)N * 64 * sizeof(float));
        cudaMemsetAsync(statsp, 0, 384 * sizeof(float));
        edge_kernel<<<edgeBlocks, 256>>>(ei, ea, bond_emb + (size_t)l * 3 * 8 * 64,
                                         (l > 0) ? 1 : 0, E, N);
        gemm1_kernel<<<rowBlocks, 512, GEMM1_SMEM>>>((l > 0) ? 1 : 0, eps + l,
                                                     W1 + (size_t)l * 64 * 128,
                                                     b1 + (size_t)l * 128, N);
        reduce1_kernel<<<1, 128>>>(bn1_g + (size_t)l * 128, bn1_b + (size_t)l * 128, invN);
        gemm2_kernel<<<rowBlocks, 512, GEMM2_SMEM>>>(W2 + (size_t)l * 128 * 64,
                                                     b2 + (size_t)l * 64, N);
        reduce2_kernel<<<1, 64>>>(bn_g + (size_t)l * 64, bn_b + (size_t)l * 64, invN);
    }

    final_kernel<<<nodeBlocks, 256>>>(batch, (float*)d_out, N, (long long)out_size);
}

// round 8
// speedup vs baseline: 1.3197x; 1.0397x over previous
#include <cuda_runtime.h>
#include <cuda_bf16.h>

#define EMB 64
#define MAXN 100000
#define MAXE 1000000
#define NLAYER 4

// ---------------- scratch (__device__ globals: allocation-free) ----------------
__device__ float g_h[(size_t)MAXN * 64];          // current node features (raw, pre-affine)
__device__ float g_agg[(size_t)MAXN * 64];        // scatter-add target
__device__ float g_y[(size_t)MAXN * 128];         // GEMM1 output
__device__ float g_stats[384];                    // [sum128, sq128, sum64, sq64] (BSS zero)
__device__ float g_aff1[256];                     // BN1 affine: a[128], c[128]
__device__ float g_aff2[128];                     // outer BN affine: a[64], c[64]

// ---------------- f32x2 packed-FMA helpers (sm_103a) ----------------------------
__device__ __forceinline__ void ffma2(unsigned long long& d, unsigned long long a,
                                      unsigned long long b) {
    asm("fma.rn.f32x2 %0, %1, %2, %0;" : "+l"(d) : "l"(a), "l"(b));
}
__device__ __forceinline__ unsigned long long bcast2(float v) {
    unsigned long long r;
    asm("mov.b64 %0, {%1, %1};" : "=l"(r) : "f"(v));
    return r;
}
__device__ __forceinline__ float2 unpack2(unsigned long long v) {
    float2 r;
    asm("mov.b64 {%0, %1}, %2;" : "=f"(r.x), "=f"(r.y) : "l"(v));
    return r;
}
__device__ __forceinline__ float warp_sum(float v) {
#pragma unroll
    for (int o = 16; o > 0; o >>= 1) v += __shfl_xor_sync(0xffffffffu, v, o);
    return v;
}

// ---------------- init affine to identity (for layer 0 consumers) --------------
__global__ void init_aff_kernel() {
    int t = threadIdx.x;
    if (t < 64) g_aff2[t] = 1.0f;
    else        g_aff2[t] = 0.0f;   // t in [64,128)
}

// ---------------- atom encoder: h[n] = sum_c atom_emb[c][x[n,c]] ----------------
__global__ void atom_kernel(const int* __restrict__ x, const float* __restrict__ aemb, int N) {
    int t = blockIdx.x * blockDim.x + threadIdx.x;
    int node = t >> 4, lane = t & 15;
    if (node >= N) return;
    float4 s = make_float4(0.f, 0.f, 0.f, 0.f);
#pragma unroll
    for (int c = 0; c < 9; c++) {
        int v = __ldg(&x[node * 9 + c]);
        float4 e = *(const float4*)&aemb[((size_t)(c * 64 + v)) * 64 + lane * 4];
        s.x += e.x; s.y += e.y; s.z += e.z; s.w += e.w;
    }
    *(float4*)&g_h[(size_t)node * 64 + lane * 4] = s;
}

// ---------------- edge kernel: agg[dst] += relu(heff[src] + ee) -----------------
// EPB=256 edges per 256-thread block. Phase 1 stages all per-edge indices into
// smem with coalesced loads (removes the 16x-redundant scalar LDGs per edge);
// phase 2: 16 groups of 16 lanes each process 16 edges, indices via LDS broadcast.
#define EPB 256
__global__ __launch_bounds__(256) void edge_kernel(const int* __restrict__ ei, const int* __restrict__ ea,
                            const float* __restrict__ bt /* 3*8*64 for this layer */,
                            int doRelu, int E, int N) {
    __shared__ float sbt[3 * 8 * 64];
    __shared__ float sa[64], sc[64];
    __shared__ int s_src[EPB], s_dst[EPB];
    __shared__ int s_ea[EPB * 3];
    int tid = threadIdx.x;
    for (int t = tid; t < 1536; t += 256) sbt[t] = bt[t];
    if (tid < 64) { sa[tid] = g_aff2[tid]; sc[tid] = g_aff2[64 + tid]; }

    int base = blockIdx.x * EPB;
    int nE = min(EPB, E - base);          // edges in this block
    // stage src/dst (coalesced)
    if (tid < nE) {
        s_src[tid] = __ldg(&ei[base + tid]);
        s_dst[tid] = __ldg(&ei[E + base + tid]);
    }
    // stage edge_attr (coalesced over 3*nE ints)
#pragma unroll
    for (int t3 = tid; t3 < 3 * EPB; t3 += 256)
        if (t3 < 3 * nE) s_ea[t3] = __ldg(&ea[(size_t)base * 3 + t3]);
    __syncthreads();

    int lane = tid & 15, grp = tid >> 4;
    float4 a4 = *(float4*)&sa[lane * 4];
    float4 c4 = *(float4*)&sc[lane * 4];

#pragma unroll 4
    for (int i = 0; i < EPB / 16; i++) {
        int le = i * 16 + grp;
        if (le >= nE) continue;
        int src = s_src[le];
        int dst = s_dst[le];
        int b0 = s_ea[le * 3 + 0], b1 = s_ea[le * 3 + 1], b2 = s_ea[le * 3 + 2];
        float4 e0 = *(float4*)&sbt[(0 * 8 + b0) * 64 + lane * 4];
        float4 e1 = *(float4*)&sbt[(1 * 8 + b1) * 64 + lane * 4];
        float4 e2 = *(float4*)&sbt[(2 * 8 + b2) * 64 + lane * 4];
        float4 hv = __ldg((const float4*)&g_h[(size_t)src * 64 + lane * 4]);
        // affine + optional relu (previous layer's BN folded)
        float h0 = fmaf(a4.x, hv.x, c4.x);
        float h1 = fmaf(a4.y, hv.y, c4.y);
        float h2 = fmaf(a4.z, hv.z, c4.z);
        float h3 = fmaf(a4.w, hv.w, c4.w);
        if (doRelu) { h0 = fmaxf(h0, 0.f); h1 = fmaxf(h1, 0.f); h2 = fmaxf(h2, 0.f); h3 = fmaxf(h3, 0.f); }
        float m0 = fmaxf(h0 + e0.x + e1.x + e2.x, 0.f);
        float m1 = fmaxf(h1 + e0.y + e1.y + e2.y, 0.f);
        float m2 = fmaxf(h2 + e0.z + e1.z + e2.z, 0.f);
        float m3 = fmaxf(h3 + e0.w + e1.w + e2.w, 0.f);
        float* dstp = &g_agg[(size_t)dst * 64 + lane * 4];
        asm volatile("red.global.add.v4.f32 [%0], {%1,%2,%3,%4};"
                     :: "l"(dstp), "f"(m0), "f"(m1), "f"(m2), "f"(m3) : "memory");
    }
}

// ---------------- GEMM1: Y = Z @ W1 + b1, Z = (1+eps)*heff + agg; stats(Y) -------
// block tile: 128 rows x 128 cols, K=64. 512 threads, micro 4 rows x 8 cols.
// Warp layout: tr = tid&31 (row group), tc = tid>>5 (col group) -> whole warp
// shares tc => B smem loads are broadcast; A loads are conflict-free.
// dyn smem: Zs[64][128] + Ws[64][128] + ssum[128] + ssq[128]
#define GEMM1_SMEM ((64 * 128 + 64 * 128 + 256) * sizeof(float))
__global__ __launch_bounds__(512, 2) void gemm1_kernel(int doRelu, const float* __restrict__ epsp,
                                                       const float* __restrict__ W1,
                                                       const float* __restrict__ bias1, int N) {
    extern __shared__ float sm[];
    float* Zs   = sm;                 // [k][m] 64x128
    float* Ws   = sm + 64 * 128;      // [k][n] 64x128
    float* ssum = Ws + 64 * 128;      // [128]
    float* ssq  = ssum + 128;         // [128]
    int tid = threadIdx.x;
    int rowBase = blockIdx.x * 128;
    float ope = 1.0f + *epsp;

    for (int t = tid; t < (64 * 128) / 4; t += 512)
        ((float4*)Ws)[t] = ((const float4*)W1)[t];

    for (int t = tid; t < 128 * 16; t += 512) {
        int r = t >> 4, kq = t & 15;
        int grow = rowBase + r;
        float4 hv, av;
        if (grow < N) {
            hv = ((const float4*)(g_h  + (size_t)grow * 64))[kq];
            av = ((const float4*)(g_agg + (size_t)grow * 64))[kq];
        } else {
            hv = make_float4(0.f, 0.f, 0.f, 0.f); av = hv;
        }
        float4 a4 = *(const float4*)(g_aff2 + kq * 4);
        float4 c4 = *(const float4*)(g_aff2 + 64 + kq * 4);
        float h0 = fmaf(a4.x, hv.x, c4.x), h1 = fmaf(a4.y, hv.y, c4.y);
        float h2 = fmaf(a4.z, hv.z, c4.z), h3 = fmaf(a4.w, hv.w, c4.w);
        if (doRelu) { h0 = fmaxf(h0, 0.f); h1 = fmaxf(h1, 0.f); h2 = fmaxf(h2, 0.f); h3 = fmaxf(h3, 0.f); }
        Zs[(kq * 4 + 0) * 128 + r] = fmaf(ope, h0, av.x);
        Zs[(kq * 4 + 1) * 128 + r] = fmaf(ope, h1, av.y);
        Zs[(kq * 4 + 2) * 128 + r] = fmaf(ope, h2, av.z);
        Zs[(kq * 4 + 3) * 128 + r] = fmaf(ope, h3, av.w);
    }
    if (tid < 128) { ssum[tid] = 0.f; ssq[tid] = 0.f; }
    __syncthreads();

    int tr = tid & 31;   // rows tr*4 .. tr*4+3
    int tc = tid >> 5;   // cols tc*8 .. tc*8+7 (whole warp shares tc)
    // acc2[ip][j]: rows (tr*4 + 2ip, tr*4 + 2ip + 1), col tc*8 + j
    unsigned long long acc2[2][8];
#pragma unroll
    for (int i = 0; i < 2; i++)
#pragma unroll
        for (int j = 0; j < 8; j++) acc2[i][j] = 0ull;

#pragma unroll 4
    for (int k = 0; k < 64; ++k) {
        ulonglong2 ap = *(ulonglong2*)(Zs + k * 128 + tr * 4);   // 2 row-pairs
        float4 bv0 = *(float4*)(Ws + k * 128 + tc * 8);          // broadcast
        float4 bv1 = *(float4*)(Ws + k * 128 + tc * 8 + 4);      // broadcast
        {
            unsigned long long b0 = bcast2(bv0.x), b1 = bcast2(bv0.y),
                               b2 = bcast2(bv0.z), b3 = bcast2(bv0.w);
            ffma2(acc2[0][0], ap.x, b0); ffma2(acc2[1][0], ap.y, b0);
            ffma2(acc2[0][1], ap.x, b1); ffma2(acc2[1][1], ap.y, b1);
            ffma2(acc2[0][2], ap.x, b2); ffma2(acc2[1][2], ap.y, b2);
            ffma2(acc2[0][3], ap.x, b3); ffma2(acc2[1][3], ap.y, b3);
        }
        {
            unsigned long long b4 = bcast2(bv1.x), b5 = bcast2(bv1.y),
                               b6 = bcast2(bv1.z), b7 = bcast2(bv1.w);
            ffma2(acc2[0][4], ap.x, b4); ffma2(acc2[1][4], ap.y, b4);
            ffma2(acc2[0][5], ap.x, b5); ffma2(acc2[1][5], ap.y, b5);
            ffma2(acc2[0][6], ap.x, b6); ffma2(acc2[1][6], ap.y, b6);
            ffma2(acc2[0][7], ap.x, b7); ffma2(acc2[1][7], ap.y, b7);
        }
    }

    float4 bb0 = *(const float4*)(bias1 + tc * 8);
    float4 bb1 = *(const float4*)(bias1 + tc * 8 + 4);
    float bj[8] = {bb0.x, bb0.y, bb0.z, bb0.w, bb1.x, bb1.y, bb1.z, bb1.w};
    float csum[8] = {0, 0, 0, 0, 0, 0, 0, 0}, csq[8] = {0, 0, 0, 0, 0, 0, 0, 0};
#pragma unroll
    for (int ip = 0; ip < 2; ip++) {
#pragma unroll
        for (int half = 0; half < 2; half++) {
            int grow = rowBase + tr * 4 + ip * 2 + half;
            if (grow < N) {
                float y[8];
#pragma unroll
                for (int j = 0; j < 8; j++) {
                    float2 p = unpack2(acc2[ip][j]);
                    float v = (half == 0 ? p.x : p.y) + bj[j];
                    y[j] = v;
                    csum[j] += v;
                    csq[j]  += v * v;
                }
                float* yp = g_y + (size_t)grow * 128 + tc * 8;
                *(float4*)yp       = make_float4(y[0], y[1], y[2], y[3]);
                *(float4*)(yp + 4) = make_float4(y[4], y[5], y[6], y[7]);
            }
        }
    }
    // warp-level reduce (all lanes share tc), then one atomic per column per warp
#pragma unroll
    for (int j = 0; j < 8; j++) {
        float s = warp_sum(csum[j]);
        float q = warp_sum(csq[j]);
        if ((tid & 31) == 0) {
            atomicAdd(&ssum[tc * 8 + j], s);
            atomicAdd(&ssq [tc * 8 + j], q);
        }
    }
    __syncthreads();
    if (tid < 128) {
        atomicAdd(&g_stats[tid],       ssum[tid]);
        atomicAdd(&g_stats[128 + tid], ssq[tid]);
    }
}

// ---------------- reduce1: stats -> BN1 affine (a1,c1); zero consumed stats -----
__global__ void reduce1_kernel(const float* __restrict__ gam, const float* __restrict__ bet, float invN) {
    int c = threadIdx.x;   // 128
    float s = g_stats[c], sq = g_stats[128 + c];
    float m = s * invN;
    float v = sq * invN - m * m;
    float r = rsqrtf(v + 1e-5f);
    float a = gam[c] * r;
    g_aff1[c]       = a;
    g_aff1[128 + c] = bet[c] - m * a;
    g_stats[c] = 0.f;            // reset for next layer (keeps BSS-zero invariant)
    g_stats[128 + c] = 0.f;
}

// ---------------- GEMM2: T = relu(aff1(Y)) @ W2 + b2; stats(T); T -> g_h --------
// block tile: 128 rows x 64 cols, K=128 in 2 chunks of 64. 512 threads,
// micro 4 rows x 4 cols. Warp shares tc => B broadcast.
// dyn smem: Ys[64][128] + Ws2[64][64] + ssum[64] + ssq[64]
#define GEMM2_SMEM ((64 * 128 + 64 * 64 + 128) * sizeof(float))
__global__ __launch_bounds__(512, 2) void gemm2_kernel(const float* __restrict__ W2,
                                                       const float* __restrict__ bias2, int N) {
    extern __shared__ float sm[];
    float* Ys   = sm;               // [k][m] 64x128 (per chunk)
    float* Ws2  = sm + 64 * 128;    // [k][n] 64x64
    float* ssum = Ws2 + 64 * 64;    // [64]
    float* ssq  = ssum + 64;        // [64]
    int tid = threadIdx.x;
    int rowBase = blockIdx.x * 128;
    int tr = tid & 31;   // rows tr*4 .. +3
    int tc = tid >> 5;   // cols tc*4 .. +3

    if (tid < 64) { ssum[tid] = 0.f; ssq[tid] = 0.f; }

    // acc2[ip][j]: rows (tr*4 + 2ip, tr*4 + 2ip + 1), col tc*4 + j
    unsigned long long acc2[2][4];
#pragma unroll
    for (int i = 0; i < 2; i++)
#pragma unroll
        for (int j = 0; j < 4; j++) acc2[i][j] = 0ull;

#pragma unroll 1
    for (int kc = 0; kc < 2; ++kc) {
        if (kc) __syncthreads();   // protect smem reuse across chunks
        for (int t = tid; t < (64 * 64) / 4; t += 512)
            ((float4*)Ws2)[t] = ((const float4*)(W2 + kc * 64 * 64))[t];
        for (int t = tid; t < 128 * 16; t += 512) {
            int r = t >> 4, kq = t & 15;
            int grow = rowBase + r;
            float4 yv = (grow < N) ? ((const float4*)(g_y + (size_t)grow * 128))[kc * 16 + kq]
                                   : make_float4(0.f, 0.f, 0.f, 0.f);
            int kb = kc * 64 + kq * 4;
            float4 a4 = *(const float4*)(g_aff1 + kb);
            float4 c4 = *(const float4*)(g_aff1 + 128 + kb);
            Ys[(kq * 4 + 0) * 128 + r] = fmaxf(fmaf(a4.x, yv.x, c4.x), 0.f);
            Ys[(kq * 4 + 1) * 128 + r] = fmaxf(fmaf(a4.y, yv.y, c4.y), 0.f);
            Ys[(kq * 4 + 2) * 128 + r] = fmaxf(fmaf(a4.z, yv.z, c4.z), 0.f);
            Ys[(kq * 4 + 3) * 128 + r] = fmaxf(fmaf(a4.w, yv.w, c4.w), 0.f);
        }
        __syncthreads();
#pragma unroll 4
        for (int k = 0; k < 64; ++k) {
            ulonglong2 ap = *(ulonglong2*)(Ys + k * 128 + tr * 4);
            float4 bv = *(float4*)(Ws2 + k * 64 + tc * 4);   // broadcast
            unsigned long long b0 = bcast2(bv.x), b1 = bcast2(bv.y),
                               b2 = bcast2(bv.z), b3 = bcast2(bv.w);
            ffma2(acc2[0][0], ap.x, b0); ffma2(acc2[1][0], ap.y, b0);
            ffma2(acc2[0][1], ap.x, b1); ffma2(acc2[1][1], ap.y, b1);
            ffma2(acc2[0][2], ap.x, b2); ffma2(acc2[1][2], ap.y, b2);
            ffma2(acc2[0][3], ap.x, b3); ffma2(acc2[1][3], ap.y, b3);
        }
    }

    float4 bbv = *(const float4*)(bias2 + tc * 4);
    float bj[4] = {bbv.x, bbv.y, bbv.z, bbv.w};
    float csum[4] = {0, 0, 0, 0}, csq[4] = {0, 0, 0, 0};
#pragma unroll
    for (int ip = 0; ip < 2; ip++) {
#pragma unroll
        for (int half = 0; half < 2; half++) {
            int grow = rowBase + tr * 4 + ip * 2 + half;
            if (grow < N) {
                float tv[4];
#pragma unroll
                for (int j = 0; j < 4; j++) {
                    float2 p = unpack2(acc2[ip][j]);
                    float v = (half == 0 ? p.x : p.y) + bj[j];
                    tv[j] = v;
                    csum[j] += v;
                    csq[j]  += v * v;
                }
                *(float4*)(g_h + (size_t)grow * 64 + tc * 4) = make_float4(tv[0], tv[1], tv[2], tv[3]);
            }
        }
    }
#pragma unroll
    for (int j = 0; j < 4; j++) {
        float s = warp_sum(csum[j]);
        float q = warp_sum(csq[j]);
        if ((tid & 31) == 0) {
            atomicAdd(&ssum[tc * 4 + j], s);
            atomicAdd(&ssq [tc * 4 + j], q);
        }
    }
    __syncthreads();
    if (tid < 64) {
        atomicAdd(&g_stats[256 + tid], ssum[tid]);
        atomicAdd(&g_stats[320 + tid], ssq[tid]);
    }
}

// ---------------- reduce2: stats -> outer BN affine (a2,c2); zero stats ---------
__global__ void reduce2_kernel(const float* __restrict__ gam, const float* __restrict__ bet, float invN) {
    int c = threadIdx.x;   // 64
    float s = g_stats[256 + c], sq = g_stats[320 + c];
    float m = s * invN;
    float v = sq * invN - m * m;
    float r = rsqrtf(v + 1e-5f);
    float a = gam[c] * r;
    g_aff2[c]      = a;
    g_aff2[64 + c] = bet[c] - m * a;
    g_stats[256 + c] = 0.f;      // reset for next layer
    g_stats[320 + c] = 0.f;
}

// ---------------- final: out = aff2(g_h) (no relu) ; append batch ---------------
__global__ void final_kernel(const int* __restrict__ batch, float* __restrict__ out,
                             int N, long long outn) {
    int t = blockIdx.x * blockDim.x + threadIdx.x;
    int node = t >> 4, lane = t & 15;
    if (node < N) {
        float4 a4 = *(const float4*)(g_aff2 + lane * 4);
        float4 c4 = *(const float4*)(g_aff2 + 64 + lane * 4);
        float4 tv = *(const float4*)(g_h + (size_t)node * 64 + lane * 4);
        float4 o;
        o.x = fmaf(a4.x, tv.x, c4.x);
        o.y = fmaf(a4.y, tv.y, c4.y);
        o.z = fmaf(a4.z, tv.z, c4.z);
        o.w = fmaf(a4.w, tv.w, c4.w);
        *(float4*)(out + (size_t)node * 64 + lane * 4) = o;
    }
    if (t < N && outn >= (long long)N * 64 + N)
        out[(size_t)N * 64 + t] = (float)batch[t];
}

// -------------------------------- host side ------------------------------------
extern "C" void kernel_launch(void* const* d_in, const int* in_sizes, int n_in,
                              void* d_out, int out_size) {
    const int*   x        = (const int*)d_in[0];
    const int*   ei       = (const int*)d_in[1];
    const int*   ea       = (const int*)d_in[2];
    const int*   batch    = (const int*)d_in[3];
    const float* atom_emb = (const float*)d_in[4];
    const float* bond_emb = (const float*)d_in[5];
    const float* eps      = (const float*)d_in[6];
    const float* W1       = (const float*)d_in[7];
    const float* b1       = (const float*)d_in[8];
    const float* bn1_g    = (const float*)d_in[9];
    const float* bn1_b    = (const float*)d_in[10];
    const float* W2       = (const float*)d_in[11];
    const float* b2       = (const float*)d_in[12];
    const float* bn_g     = (const float*)d_in[13];
    const float* bn_b     = (const float*)d_in[14];

    int N = in_sizes[0] / 9;
    int E = in_sizes[1] / 2;
    float invN = 1.0f / (float)N;

    // one-time host-side setup (symbol addresses / smem opt-in)
    static void* aggp = nullptr;
    if (!aggp) {
        cudaFuncSetAttribute(gemm1_kernel, cudaFuncAttributeMaxDynamicSharedMemorySize, (int)GEMM1_SMEM);
        cudaFuncSetAttribute(gemm2_kernel, cudaFuncAttributeMaxDynamicSharedMemorySize, (int)GEMM2_SMEM);
        cudaGetSymbolAddress(&aggp, g_agg);
    }

    int nodeBlocks = (N * 16 + 255) / 256;
    int edgeBlocks = (E + EPB - 1) / EPB;
    int rowBlocks  = (N + 127) / 128;

    atom_kernel<<<nodeBlocks, 256>>>(x, atom_emb, N);
    init_aff_kernel<<<1, 128>>>();

    for (int l = 0; l < NLAYER; ++l) {
        cudaMemsetAsync(aggp, 0, (size_t)N * 64 * sizeof(float));
        edge_kernel<<<edgeBlocks, 256>>>(ei, ea, bond_emb + (size_t)l * 3 * 8 * 64,
                                         (l > 0) ? 1 : 0, E, N);
        gemm1_kernel<<<rowBlocks, 512, GEMM1_SMEM>>>((l > 0) ? 1 : 0, eps + l,
                                                     W1 + (size_t)l * 64 * 128,
                                                     b1 + (size_t)l * 128, N);
        reduce1_kernel<<<1, 128>>>(bn1_g + (size_t)l * 128, bn1_b + (size_t)l * 128, invN);
        gemm2_kernel<<<rowBlocks, 512, GEMM2_SMEM>>>(W2 + (size_t)l * 128 * 64,
                                                     b2 + (size_t)l * 64, N);
        reduce2_kernel<<<1, 64>>>(bn_g + (size_t)l * 64, bn_b + (size_t)l * 64, invN);
    }

    final_kernel<<<nodeBlocks, 256>>>(batch, (float*)d_out, N, (long long)out_size);
}

// round 10
// speedup vs baseline: 1.3379x; 1.0138x over previous
#include <cuda_runtime.h>
#include <cuda_bf16.h>

#define EMB 64
#define MAXN 100000
#define MAXE 1000000
#define NLAYER 4

// ---------------- scratch (__device__ globals: allocation-free) ----------------
__device__ float g_h[(size_t)MAXN * 64];          // current node features (raw, pre-affine)
__device__ float g_agg[(size_t)MAXN * 64];        // aggregation result
__device__ float g_y[(size_t)MAXN * 128];         // GEMM1 output
__device__ float g_stats[384];                    // [sum128, sq128, sum64, sq64] (BSS zero)
__device__ float g_aff1[256];                     // BN1 affine: a[128], c[128]
__device__ float g_aff2[128];                     // outer BN affine: a[64], c[64]
// CSR build scratch (all re-established every call; g_deg zeroed by scanC)
__device__ int  g_deg[MAXN];
__device__ int  g_rowptr[MAXN + 1];
__device__ int  g_part[512];
__device__ int  g_cursor[MAXN];
__device__ int2 g_edge[MAXE];                     // {src, b0|b1<<8|b2<<16}

// ---------------- f32x2 packed-FMA helpers (sm_103a) ----------------------------
__device__ __forceinline__ void ffma2(unsigned long long& d, unsigned long long a,
                                      unsigned long long b) {
    asm("fma.rn.f32x2 %0, %1, %2, %0;" : "+l"(d) : "l"(a), "l"(b));
}
__device__ __forceinline__ unsigned long long bcast2(float v) {
    unsigned long long r;
    asm("mov.b64 %0, {%1, %1};" : "=l"(r) : "f"(v));
    return r;
}
__device__ __forceinline__ float2 unpack2(unsigned long long v) {
    float2 r;
    asm("mov.b64 {%0, %1}, %2;" : "=f"(r.x), "=f"(r.y) : "l"(v));
    return r;
}
__device__ __forceinline__ float warp_sum(float v) {
#pragma unroll
    for (int o = 16; o > 0; o >>= 1) v += __shfl_xor_sync(0xffffffffu, v, o);
    return v;
}

// ---------------- init affine to identity (for layer 0 consumers) --------------
__global__ void init_aff_kernel() {
    int t = threadIdx.x;
    if (t < 64) g_aff2[t] = 1.0f;
    else        g_aff2[t] = 0.0f;   // t in [64,128)
}

// ---------------- atom encoder: h[n] = sum_c atom_emb[c][x[n,c]] ----------------
__global__ void atom_kernel(const int* __restrict__ x, const float* __restrict__ aemb, int N) {
    int t = blockIdx.x * blockDim.x + threadIdx.x;
    int node = t >> 4, lane = t & 15;
    if (node >= N) return;
    float4 s = make_float4(0.f, 0.f, 0.f, 0.f);
#pragma unroll
    for (int c = 0; c < 9; c++) {
        int v = __ldg(&x[node * 9 + c]);
        float4 e = *(const float4*)&aemb[((size_t)(c * 64 + v)) * 64 + lane * 4];
        s.x += e.x; s.y += e.y; s.z += e.z; s.w += e.w;
    }
    *(float4*)&g_h[(size_t)node * 64 + lane * 4] = s;
}

// ================= CSR build (once per call; edge structure is layer-invariant) =
__global__ void hist_kernel(const int* __restrict__ ei, int E) {
    int e = blockIdx.x * blockDim.x + threadIdx.x;
    if (e < E) atomicAdd(&g_deg[__ldg(&ei[E + e])], 1);
}

// scanA: per-512 block exclusive scan of g_deg -> g_rowptr (local), totals -> g_part
__global__ __launch_bounds__(512) void scanA_kernel(int N) {
    __shared__ int s[512];
    int tx = threadIdx.x;
    int i = blockIdx.x * 512 + tx;
    int d = (i < N) ? g_deg[i] : 0;
    s[tx] = d;
    __syncthreads();
#pragma unroll
    for (int o = 1; o < 512; o <<= 1) {
        int v = (tx >= o) ? s[tx - o] : 0;
        __syncthreads();
        if (tx >= o) s[tx] += v;
        __syncthreads();
    }
    if (i < N) g_rowptr[i] = s[tx] - d;      // exclusive within block
    if (tx == 511) g_part[blockIdx.x] = s[511];
}

// scanB: one block, exclusive scan of block totals (nb <= 512)
__global__ __launch_bounds__(512) void scanB_kernel(int nb) {
    __shared__ int s[512];
    int tx = threadIdx.x;
    int d = (tx < nb) ? g_part[tx] : 0;
    s[tx] = d;
    __syncthreads();
#pragma unroll
    for (int o = 1; o < 512; o <<= 1) {
        int v = (tx >= o) ? s[tx - o] : 0;
        __syncthreads();
        if (tx >= o) s[tx] += v;
        __syncthreads();
    }
    if (tx < nb) g_part[tx] = s[tx] - d;
}

// scanC: add block offsets; init cursor; re-zero deg (keeps replay invariant)
__global__ __launch_bounds__(512) void scanC_kernel(int N, int E) {
    int i = blockIdx.x * 512 + threadIdx.x;
    if (i < N) {
        int v = g_rowptr[i] + g_part[blockIdx.x];
        g_rowptr[i] = v;
        g_cursor[i] = v;
        g_deg[i] = 0;
    }
    if (i == 0) g_rowptr[N] = E;
}

// scatter: bucket edges by dst; pack bond attrs (read ea ONCE per call)
__global__ void scatter_kernel(const int* __restrict__ ei, const int* __restrict__ ea, int E) {
    int e = blockIdx.x * blockDim.x + threadIdx.x;
    if (e >= E) return;
    int src = __ldg(&ei[e]);
    int dst = __ldg(&ei[E + e]);
    int pk = __ldg(&ea[e * 3 + 0]) | (__ldg(&ea[e * 3 + 1]) << 8) | (__ldg(&ea[e * 3 + 2]) << 16);
    int pos = atomicAdd(&g_cursor[dst], 1);
    g_edge[pos] = make_int2(src, pk);
}

// ---------------- agg kernel: agg[n] = sum_{e in CSR[n]} relu(heff[src]+ee) -----
// 16 lanes per dst node, 16 nodes per 256-thread block. No atomics, one write.
__global__ __launch_bounds__(256) void agg_kernel(const float* __restrict__ bt, int doRelu, int N) {
    __shared__ float sbt[3 * 8 * 64];
    __shared__ float sa[64], sc[64];
    int tid = threadIdx.x;
    for (int t = tid; t < 1536; t += 256) sbt[t] = bt[t];
    if (tid < 64) { sa[tid] = g_aff2[tid]; sc[tid] = g_aff2[64 + tid]; }
    __syncthreads();

    int lane = tid & 15, grp = tid >> 4;
    int n = blockIdx.x * 16 + grp;
    if (n >= N) return;
    int e0 = __ldg(&g_rowptr[n]);
    int e1 = __ldg(&g_rowptr[n + 1]);
    float4 a4 = *(float4*)&sa[lane * 4];
    float4 c4 = *(float4*)&sc[lane * 4];
    float4 acc = make_float4(0.f, 0.f, 0.f, 0.f);

    int2 ed;
    if (e0 < e1) ed = __ldg(&g_edge[e0]);
#pragma unroll 1
    for (int i = e0; i < e1; i++) {
        int2 nxt;
        if (i + 1 < e1) nxt = __ldg(&g_edge[i + 1]);   // prefetch
        int src = ed.x;
        int b0 = ed.y & 255, b1 = (ed.y >> 8) & 255, b2 = (ed.y >> 16) & 255;
        float4 hv = __ldg((const float4*)&g_h[(size_t)src * 64 + lane * 4]);
        float4 e0v = *(float4*)&sbt[(0 * 8 + b0) * 64 + lane * 4];
        float4 e1v = *(float4*)&sbt[(1 * 8 + b1) * 64 + lane * 4];
        float4 e2v = *(float4*)&sbt[(2 * 8 + b2) * 64 + lane * 4];
        float h0 = fmaf(a4.x, hv.x, c4.x);
        float h1 = fmaf(a4.y, hv.y, c4.y);
        float h2 = fmaf(a4.z, hv.z, c4.z);
        float h3 = fmaf(a4.w, hv.w, c4.w);
        if (doRelu) { h0 = fmaxf(h0, 0.f); h1 = fmaxf(h1, 0.f); h2 = fmaxf(h2, 0.f); h3 = fmaxf(h3, 0.f); }
        acc.x += fmaxf(h0 + e0v.x + e1v.x + e2v.x, 0.f);
        acc.y += fmaxf(h1 + e0v.y + e1v.y + e2v.y, 0.f);
        acc.z += fmaxf(h2 + e0v.z + e1v.z + e2v.z, 0.f);
        acc.w += fmaxf(h3 + e0v.w + e1v.w + e2v.w, 0.f);
        ed = nxt;
    }
    *(float4*)&g_agg[(size_t)n * 64 + lane * 4] = acc;   // covers zero-degree too
}

// ---------------- GEMM1: Y = Z @ W1 + b1, Z = (1+eps)*heff + agg; stats(Y) -------
#define GEMM1_SMEM ((64 * 128 + 64 * 128 + 256) * sizeof(float))
__global__ __launch_bounds__(512, 2) void gemm1_kernel(int doRelu, const float* __restrict__ epsp,
                                                       const float* __restrict__ W1,
                                                       const float* __restrict__ bias1, int N) {
    extern __shared__ float sm[];
    float* Zs   = sm;                 // [k][m] 64x128
    float* Ws   = sm + 64 * 128;      // [k][n] 64x128
    float* ssum = Ws + 64 * 128;      // [128]
    float* ssq  = ssum + 128;         // [128]
    int tid = threadIdx.x;
    int rowBase = blockIdx.x * 128;
    float ope = 1.0f + *epsp;

    for (int t = tid; t < (64 * 128) / 4; t += 512)
        ((float4*)Ws)[t] = ((const float4*)W1)[t];

    for (int t = tid; t < 128 * 16; t += 512) {
        int r = t >> 4, kq = t & 15;
        int grow = rowBase + r;
        float4 hv, av;
        if (grow < N) {
            hv = ((const float4*)(g_h  + (size_t)grow * 64))[kq];
            av = ((const float4*)(g_agg + (size_t)grow * 64))[kq];
        } else {
            hv = make_float4(0.f, 0.f, 0.f, 0.f); av = hv;
        }
        float4 a4 = *(const float4*)(g_aff2 + kq * 4);
        float4 c4 = *(const float4*)(g_aff2 + 64 + kq * 4);
        float h0 = fmaf(a4.x, hv.x, c4.x), h1 = fmaf(a4.y, hv.y, c4.y);
        float h2 = fmaf(a4.z, hv.z, c4.z), h3 = fmaf(a4.w, hv.w, c4.w);
        if (doRelu) { h0 = fmaxf(h0, 0.f); h1 = fmaxf(h1, 0.f); h2 = fmaxf(h2, 0.f); h3 = fmaxf(h3, 0.f); }
        Zs[(kq * 4 + 0) * 128 + r] = fmaf(ope, h0, av.x);
        Zs[(kq * 4 + 1) * 128 + r] = fmaf(ope, h1, av.y);
        Zs[(kq * 4 + 2) * 128 + r] = fmaf(ope, h2, av.z);
        Zs[(kq * 4 + 3) * 128 + r] = fmaf(ope, h3, av.w);
    }
    if (tid < 128) { ssum[tid] = 0.f; ssq[tid] = 0.f; }
    __syncthreads();

    int tr = tid & 31;   // rows tr*4 .. tr*4+3
    int tc = tid >> 5;   // cols tc*8 .. tc*8+7 (whole warp shares tc)
    unsigned long long acc2[2][8];
#pragma unroll
    for (int i = 0; i < 2; i++)
#pragma unroll
        for (int j = 0; j < 8; j++) acc2[i][j] = 0ull;

#pragma unroll 4
    for (int k = 0; k < 64; ++k) {
        ulonglong2 ap = *(ulonglong2*)(Zs + k * 128 + tr * 4);   // 2 row-pairs
        float4 bv0 = *(float4*)(Ws + k * 128 + tc * 8);          // broadcast
        float4 bv1 = *(float4*)(Ws + k * 128 + tc * 8 + 4);      // broadcast
        {
            unsigned long long b0 = bcast2(bv0.x), b1 = bcast2(bv0.y),
                               b2 = bcast2(bv0.z), b3 = bcast2(bv0.w);
            ffma2(acc2[0][0], ap.x, b0); ffma2(acc2[1][0], ap.y, b0);
            ffma2(acc2[0][1], ap.x, b1); ffma2(acc2[1][1], ap.y, b1);
            ffma2(acc2[0][2], ap.x, b2); ffma2(acc2[1][2], ap.y, b2);
            ffma2(acc2[0][3], ap.x, b3); ffma2(acc2[1][3], ap.y, b3);
        }
        {
            unsigned long long b4 = bcast2(bv1.x), b5 = bcast2(bv1.y),
                               b6 = bcast2(bv1.z), b7 = bcast2(bv1.w);
            ffma2(acc2[0][4], ap.x, b4); ffma2(acc2[1][4], ap.y, b4);
            ffma2(acc2[0][5], ap.x, b5); ffma2(acc2[1][5], ap.y, b5);
            ffma2(acc2[0][6], ap.x, b6); ffma2(acc2[1][6], ap.y, b6);
            ffma2(acc2[0][7], ap.x, b7); ffma2(acc2[1][7], ap.y, b7);
        }
    }

    float4 bb0 = *(const float4*)(bias1 + tc * 8);
    float4 bb1 = *(const float4*)(bias1 + tc * 8 + 4);
    float bj[8] = {bb0.x, bb0.y, bb0.z, bb0.w, bb1.x, bb1.y, bb1.z, bb1.w};
    float csum[8] = {0, 0, 0, 0, 0, 0, 0, 0}, csq[8] = {0, 0, 0, 0, 0, 0, 0, 0};
#pragma unroll
    for (int ip = 0; ip < 2; ip++) {
#pragma unroll
        for (int half = 0; half < 2; half++) {
            int grow = rowBase + tr * 4 + ip * 2 + half;
            if (grow < N) {
                float y[8];
#pragma unroll
                for (int j = 0; j < 8; j++) {
                    float2 p = unpack2(acc2[ip][j]);
                    float v = (half == 0 ? p.x : p.y) + bj[j];
                    y[j] = v;
                    csum[j] += v;
                    csq[j]  += v * v;
                }
                float* yp = g_y + (size_t)grow * 128 + tc * 8;
                *(float4*)yp       = make_float4(y[0], y[1], y[2], y[3]);
                *(float4*)(yp + 4) = make_float4(y[4], y[5], y[6], y[7]);
            }
        }
    }
#pragma unroll
    for (int j = 0; j < 8; j++) {
        float s = warp_sum(csum[j]);
        float q = warp_sum(csq[j]);
        if ((tid & 31) == 0) {
            atomicAdd(&ssum[tc * 8 + j], s);
            atomicAdd(&ssq [tc * 8 + j], q);
        }
    }
    __syncthreads();
    if (tid < 128) {
        atomicAdd(&g_stats[tid],       ssum[tid]);
        atomicAdd(&g_stats[128 + tid], ssq[tid]);
    }
}

// ---------------- reduce1: stats -> BN1 affine (a1,c1); zero consumed stats -----
__global__ void reduce1_kernel(const float* __restrict__ gam, const float* __restrict__ bet, float invN) {
    int c = threadIdx.x;   // 128
    float s = g_stats[c], sq = g_stats[128 + c];
    float m = s * invN;
    float v = sq * invN - m * m;
    float r = rsqrtf(v + 1e-5f);
    float a = gam[c] * r;
    g_aff1[c]       = a;
    g_aff1[128 + c] = bet[c] - m * a;
    g_stats[c] = 0.f;
    g_stats[128 + c] = 0.f;
}

// ---------------- GEMM2: T = relu(aff1(Y)) @ W2 + b2; stats(T); T -> g_h --------
#define GEMM2_SMEM ((64 * 128 + 64 * 64 + 128) * sizeof(float))
__global__ __launch_bounds__(512, 2) void gemm2_kernel(const float* __restrict__ W2,
                                                       const float* __restrict__ bias2, int N) {
    extern __shared__ float sm[];
    float* Ys   = sm;               // [k][m] 64x128 (per chunk)
    float* Ws2  = sm + 64 * 128;    // [k][n] 64x64
    float* ssum = Ws2 + 64 * 64;    // [64]
    float* ssq  = ssum + 64;        // [64]
    int tid = threadIdx.x;
    int rowBase = blockIdx.x * 128;
    int tr = tid & 31;   // rows tr*4 .. +3
    int tc = tid >> 5;   // cols tc*4 .. +3

    if (tid < 64) { ssum[tid] = 0.f; ssq[tid] = 0.f; }

    unsigned long long acc2[2][4];
#pragma unroll
    for (int i = 0; i < 2; i++)
#pragma unroll
        for (int j = 0; j < 4; j++) acc2[i][j] = 0ull;

#pragma unroll 1
    for (int kc = 0; kc < 2; ++kc) {
        if (kc) __syncthreads();   // protect smem reuse across chunks
        for (int t = tid; t < (64 * 64) / 4; t += 512)
            ((float4*)Ws2)[t] = ((const float4*)(W2 + kc * 64 * 64))[t];
        for (int t = tid; t < 128 * 16; t += 512) {
            int r = t >> 4, kq = t & 15;
            int grow = rowBase + r;
            float4 yv = (grow < N) ? ((const float4*)(g_y + (size_t)grow * 128))[kc * 16 + kq]
                                   : make_float4(0.f, 0.f, 0.f, 0.f);
            int kb = kc * 64 + kq * 4;
            float4 a4 = *(const float4*)(g_aff1 + kb);
            float4 c4 = *(const float4*)(g_aff1 + 128 + kb);
            Ys[(kq * 4 + 0) * 128 + r] = fmaxf(fmaf(a4.x, yv.x, c4.x), 0.f);
            Ys[(kq * 4 + 1) * 128 + r] = fmaxf(fmaf(a4.y, yv.y, c4.y), 0.f);
            Ys[(kq * 4 + 2) * 128 + r] = fmaxf(fmaf(a4.z, yv.z, c4.z), 0.f);
            Ys[(kq * 4 + 3) * 128 + r] = fmaxf(fmaf(a4.w, yv.w, c4.w), 0.f);
        }
        __syncthreads();
#pragma unroll 4
        for (int k = 0; k < 64; ++k) {
            ulonglong2 ap = *(ulonglong2*)(Ys + k * 128 + tr * 4);
            float4 bv = *(float4*)(Ws2 + k * 64 + tc * 4);   // broadcast
            unsigned long long b0 = bcast2(bv.x), b1 = bcast2(bv.y),
                               b2 = bcast2(bv.z), b3 = bcast2(bv.w);
            ffma2(acc2[0][0], ap.x, b0); ffma2(acc2[1][0], ap.y, b0);
            ffma2(acc2[0][1], ap.x, b1); ffma2(acc2[1][1], ap.y, b1);
            ffma2(acc2[0][2], ap.x, b2); ffma2(acc2[1][2], ap.y, b2);
            ffma2(acc2[0][3], ap.x, b3); ffma2(acc2[1][3], ap.y, b3);
        }
    }

    float4 bbv = *(const float4*)(bias2 + tc * 4);
    float bj[4] = {bbv.x, bbv.y, bbv.z, bbv.w};
    float csum[4] = {0, 0, 0, 0}, csq[4] = {0, 0, 0, 0};
#pragma unroll
    for (int ip = 0; ip < 2; ip++) {
#pragma unroll
        for (int half = 0; half < 2; half++) {
            int grow = rowBase + tr * 4 + ip * 2 + half;
            if (grow < N) {
                float tv[4];
#pragma unroll
                for (int j = 0; j < 4; j++) {
                    float2 p = unpack2(acc2[ip][j]);
                    float v = (half == 0 ? p.x : p.y) + bj[j];
                    tv[j] = v;
                    csum[j] += v;
                    csq[j]  += v * v;
                }
                *(float4*)(g_h + (size_t)grow * 64 + tc * 4) = make_float4(tv[0], tv[1], tv[2], tv[3]);
            }
        }
    }
#pragma unroll
    for (int j = 0; j < 4; j++) {
        float s = warp_sum(csum[j]);
        float q = warp_sum(csq[j]);
        if ((tid & 31) == 0) {
            atomicAdd(&ssum[tc * 4 + j], s);
            atomicAdd(&ssq [tc * 4 + j], q);
        }
    }
    __syncthreads();
    if (tid < 64) {
        atomicAdd(&g_stats[256 + tid], ssum[tid]);
        atomicAdd(&g_stats[320 + tid], ssq[tid]);
    }
}

// ---------------- reduce2: stats -> outer BN affine (a2,c2); zero stats ---------
__global__ void reduce2_kernel(const float* __restrict__ gam, const float* __restrict__ bet, float invN) {
    int c = threadIdx.x;   // 64
    float s = g_stats[256 + c], sq = g_stats[320 + c];
    float m = s * invN;
    float v = sq * invN - m * m;
    float r = rsqrtf(v + 1e-5f);
    float a = gam[c] * r;
    g_aff2[c]      = a;
    g_aff2[64 + c] = bet[c] - m * a;
    g_stats[256 + c] = 0.f;
    g_stats[320 + c] = 0.f;
}

// ---------------- final: out = aff2(g_h) (no relu) ; append batch ---------------
__global__ void final_kernel(const int* __restrict__ batch, float* __restrict__ out,
                             int N, long long outn) {
    int t = blockIdx.x * blockDim.x + threadIdx.x;
    int node = t >> 4, lane = t & 15;
    if (node < N) {
        float4 a4 = *(const float4*)(g_aff2 + lane * 4);
        float4 c4 = *(const float4*)(g_aff2 + 64 + lane * 4);
        float4 tv = *(const float4*)(g_h + (size_t)node * 64 + lane * 4);
        float4 o;
        o.x = fmaf(a4.x, tv.x, c4.x);
        o.y = fmaf(a4.y, tv.y, c4.y);
        o.z = fmaf(a4.z, tv.z, c4.z);
        o.w = fmaf(a4.w, tv.w, c4.w);
        *(float4*)(out + (size_t)node * 64 + lane * 4) = o;
    }
    if (t < N && outn >= (long long)N * 64 + N)
        out[(size_t)N * 64 + t] = (float)batch[t];
}

// -------------------------------- host side ------------------------------------
extern "C" void kernel_launch(void* const* d_in, const int* in_sizes, int n_in,
                              void* d_out, int out_size) {
    const int*   x        = (const int*)d_in[0];
    const int*   ei       = (const int*)d_in[1];
    const int*   ea       = (const int*)d_in[2];
    const int*   batch    = (const int*)d_in[3];
    const float* atom_emb = (const float*)d_in[4];
    const float* bond_emb = (const float*)d_in[5];
    const float* eps      = (const float*)d_in[6];
    const float* W1       = (const float*)d_in[7];
    const float* b1       = (const float*)d_in[8];
    const float* bn1_g    = (const float*)d_in[9];
    const float* bn1_b    = (const float*)d_in[10];
    const float* W2       = (const float*)d_in[11];
    const float* b2       = (const float*)d_in[12];
    const float* bn_g     = (const float*)d_in[13];
    const float* bn_b     = (const float*)d_in[14];

    int N = in_sizes[0] / 9;
    int E = in_sizes[1] / 2;
    float invN = 1.0f / (float)N;

    // one-time host-side setup (smem opt-in)
    static bool inited = false;
    if (!inited) {
        cudaFuncSetAttribute(gemm1_kernel, cudaFuncAttributeMaxDynamicSharedMemorySize, (int)GEMM1_SMEM);
        cudaFuncSetAttribute(gemm2_kernel, cudaFuncAttributeMaxDynamicSharedMemorySize, (int)GEMM2_SMEM);
        inited = true;
    }

    int nodeBlocks = (N * 16 + 255) / 256;
    int rowBlocks  = (N + 127) / 128;
    int eBlocks    = (E + 255) / 256;
    int scanBlocks = (N + 511) / 512;      // <= 512 for MAXN=100000
    int aggBlocks  = (N + 15) / 16;

    // node features + CSR build (edge structure is shared by all 4 layers)
    atom_kernel<<<nodeBlocks, 256>>>(x, atom_emb, N);
    init_aff_kernel<<<1, 128>>>();
    hist_kernel<<<eBlocks, 256>>>(ei, E);
    scanA_kernel<<<scanBlocks, 512>>>(N);
    scanB_kernel<<<1, 512>>>(scanBlocks);
    scanC_kernel<<<scanBlocks, 512>>>(N, E);
    scatter_kernel<<<eBlocks, 256>>>(ei, ea, E);

    for (int l = 0; l < NLAYER; ++l) {
        agg_kernel<<<aggBlocks, 256>>>(bond_emb + (size_t)l * 3 * 8 * 64, (l > 0) ? 1 : 0, N);
        gemm1_kernel<<<rowBlocks, 512, GEMM1_SMEM>>>((l > 0) ? 1 : 0, eps + l,
                                                     W1 + (size_t)l * 64 * 128,
                                                     b1 + (size_t)l * 128, N);
        reduce1_kernel<<<1, 128>>>(bn1_g + (size_t)l * 128, bn1_b + (size_t)l * 128, invN);
        gemm2_kernel<<<rowBlocks, 512, GEMM2_SMEM>>>(W2 + (size_t)l * 128 * 64,
                                                     b2 + (size_t)l * 64, N);
        reduce2_kernel<<<1, 64>>>(bn_g + (size_t)l * 64, bn_b + (size_t)l * 64, invN);
    }

    final_kernel<<<nodeBlocks, 256>>>(batch, (float*)d_out, N, (long long)out_size);
}